// round 6
// baseline (speedup 1.0000x reference)
#include <cuda_runtime.h>

#define BB 8
#define SS 1024
#define EE 768
#define HH 12
#define DD 64
#define MTOT (BB*SS)      // 8192
#define N3 (3*EE)         // 2304

// Scratch (allocation-free rule: __device__ globals)
__device__ float g_q[BB*HH*SS*DD];   // [B,H,S,D]
__device__ float g_k[BB*HH*SS*DD];
__device__ float g_v[BB*HH*SS*DD];
__device__ float g_o[BB*SS*EE];      // attention output [B,S,E]

// ---------------------------------------------------------------------------
// Kernel 1: qkv = x @ w_qkv + b, scattered into q/k/v as [B,H,S,D]
// 128x128 tile, BK=8, 256 threads, 8x8 per thread. All dims exact multiples.
// ---------------------------------------------------------------------------
__global__ __launch_bounds__(256) void qkv_gemm_kernel(
    const float* __restrict__ X,     // [8192, 768]
    const float* __restrict__ W,     // [768, 2304]
    const float* __restrict__ bias)  // [2304]
{
    __shared__ float As[8][128];   // transposed: As[k][m]
    __shared__ float Bs[8][128];   // Bs[k][n]

    const int bx = blockIdx.x;     // 0..17 (N tiles)
    const int by = blockIdx.y;     // 0..63 (M tiles)
    const int tid = (int)threadIdx.x;
    const int tr = tid >> 4;       // 0..15
    const int tc = tid & 15;       // 0..15

    const int n0 = bx * 128;
    const int m0 = by * 128;

    // A-load mapping: one float4 per thread per k-step
    const int arow = tid >> 1;          // 0..127
    const int acol = (tid & 1) * 4;     // 0 or 4
    // B-load mapping
    const int brow = tid >> 5;          // 0..7
    const int bcol = (tid & 31) * 4;    // 0..124

    const float* Aptr = X + (long)(m0 + arow) * EE + acol;
    const float* Bptr = W + (long)brow * N3 + n0 + bcol;

    float acc[8][8];
    #pragma unroll
    for (int i = 0; i < 8; i++)
        #pragma unroll
        for (int j = 0; j < 8; j++) acc[i][j] = 0.f;

    for (int k0 = 0; k0 < EE; k0 += 8) {
        float4 av = *(const float4*)(Aptr + k0);
        As[acol + 0][arow] = av.x;
        As[acol + 1][arow] = av.y;
        As[acol + 2][arow] = av.z;
        As[acol + 3][arow] = av.w;
        *(float4*)&Bs[brow][bcol] = *(const float4*)(Bptr + (long)k0 * N3);
        __syncthreads();

        #pragma unroll
        for (int kk = 0; kk < 8; kk++) {
            float4 a0 = *(const float4*)&As[kk][tr * 8];
            float4 a1 = *(const float4*)&As[kk][tr * 8 + 4];
            float4 b0 = *(const float4*)&Bs[kk][tc * 8];
            float4 b1 = *(const float4*)&Bs[kk][tc * 8 + 4];
            float a[8] = {a0.x, a0.y, a0.z, a0.w, a1.x, a1.y, a1.z, a1.w};
            float b[8] = {b0.x, b0.y, b0.z, b0.w, b1.x, b1.y, b1.z, b1.w};
            #pragma unroll
            for (int i = 0; i < 8; i++)
                #pragma unroll
                for (int j = 0; j < 8; j++)
                    acc[i][j] += a[i] * b[j];
        }
        __syncthreads();
    }

    // Epilogue: +bias, scatter. Whole n-tile is inside one of q/k/v (768 = 6*128).
    const int which = n0 / EE;                      // 0=q 1=k 2=v
    float* dst = (which == 0) ? g_q : ((which == 1) ? g_k : g_v);
    const int cbase = n0 - which * EE + tc * 8;     // col within [0,768)
    const int h  = cbase >> 6;
    const int d0 = cbase & 63;                      // thread's 8 cols never cross a head

    float br[8];
    #pragma unroll
    for (int j = 0; j < 8; j++) br[j] = bias[n0 + tc * 8 + j];

    #pragma unroll
    for (int i = 0; i < 8; i++) {
        int m  = m0 + tr * 8 + i;
        int b_ = m >> 10;
        int s_ = m & 1023;
        float* p = dst + (((long)(b_ * HH + h) * SS + s_) * DD + d0);
        float4 v0 = make_float4(acc[i][0] + br[0], acc[i][1] + br[1],
                                acc[i][2] + br[2], acc[i][3] + br[3]);
        float4 v1 = make_float4(acc[i][4] + br[4], acc[i][5] + br[5],
                                acc[i][6] + br[6], acc[i][7] + br[7]);
        *(float4*)p       = v0;
        *(float4*)(p + 4) = v1;
    }
}

// ---------------------------------------------------------------------------
// Kernel 2: flash attention (fp32, online softmax).
// Block = (query-tile of 64, h, b). 256 threads, 4x4 micro-tiles.
// Smem: Qs[d][i], KPs (K^T [d][j], reused as P [j][i]), Vs[j][d] = 48KB exact.
// ---------------------------------------------------------------------------
__global__ __launch_bounds__(256) void attn_kernel()
{
    __shared__ float Qs[64][64];
    __shared__ float KPs[64][64];
    __shared__ float Vs[64][64];

    const int qt = blockIdx.x;     // 0..15
    const int h  = blockIdx.y;     // 0..11
    const int b  = blockIdx.z;     // 0..7
    const int tid = (int)threadIdx.x;
    const int tr = tid >> 4;       // 0..15 -> rows tr*4..+3
    const int tc = tid & 15;       // 0..15 -> cols tc*4..+3

    const long bh = (long)(b * HH + h) * SS;
    const float* Q = g_q + bh * DD;
    const float* K = g_k + bh * DD;
    const float* V = g_v + bh * DD;
    const int i0 = qt * 64;

    // Load Q transposed into Qs[d][i]
    {
        int i = tid >> 2;
        int dbase = (tid & 3) * 16;
        const float* src = Q + (long)(i0 + i) * DD + dbase;
        #pragma unroll
        for (int q = 0; q < 4; q++) {
            float4 v = *(const float4*)(src + q * 4);
            int d = dbase + q * 4;
            Qs[d + 0][i] = v.x;
            Qs[d + 1][i] = v.y;
            Qs[d + 2][i] = v.z;
            Qs[d + 3][i] = v.w;
        }
    }

    float m_r[4], l_r[4], acc_o[4][4];
    #pragma unroll
    for (int ii = 0; ii < 4; ii++) {
        m_r[ii] = -1e30f;
        l_r[ii] = 0.f;
        #pragma unroll
        for (int jj = 0; jj < 4; jj++) acc_o[ii][jj] = 0.f;
    }

    const float scale = 0.125f;   // 1/sqrt(64)

    for (int j0 = 0; j0 < SS; j0 += 64) {
        // K tile transposed -> KPs[d][j]
        {
            int j = tid >> 2;
            int dbase = (tid & 3) * 16;
            const float* src = K + (long)(j0 + j) * DD + dbase;
            #pragma unroll
            for (int q = 0; q < 4; q++) {
                float4 v = *(const float4*)(src + q * 4);
                int d = dbase + q * 4;
                KPs[d + 0][j] = v.x;
                KPs[d + 1][j] = v.y;
                KPs[d + 2][j] = v.z;
                KPs[d + 3][j] = v.w;
            }
        }
        // V tile direct -> Vs[j][d]
        {
            const float* src = V + (long)j0 * DD;
            #pragma unroll
            for (int r = 0; r < 4; r++) {
                int idx = tid + 256 * r;      // float4 index 0..1023
                int j = idx >> 4;
                int d = (idx & 15) * 4;
                *(float4*)&Vs[j][d] = *(const float4*)(src + j * DD + d);
            }
        }
        __syncthreads();

        // S = Q K^T (unscaled)
        float s_acc[4][4];
        #pragma unroll
        for (int ii = 0; ii < 4; ii++)
            #pragma unroll
            for (int jj = 0; jj < 4; jj++) s_acc[ii][jj] = 0.f;

        #pragma unroll 8
        for (int kk = 0; kk < 64; kk++) {
            float4 a = *(const float4*)&Qs[kk][tr * 4];     // broadcast in 16-lane group
            float4 bq = *(const float4*)&KPs[kk][tc * 4];   // conflict-free
            float av[4] = {a.x, a.y, a.z, a.w};
            float bv[4] = {bq.x, bq.y, bq.z, bq.w};
            #pragma unroll
            for (int ii = 0; ii < 4; ii++)
                #pragma unroll
                for (int jj = 0; jj < 4; jj++)
                    s_acc[ii][jj] += av[ii] * bv[jj];
        }
        __syncthreads();   // all done reading KPs; safe to overwrite with P

        // Online softmax (row groups = 16 consecutive lanes; xor<=8 stays in group)
        float p[4][4];
        #pragma unroll
        for (int ii = 0; ii < 4; ii++) {
            float mx = fmaxf(fmaxf(s_acc[ii][0], s_acc[ii][1]),
                             fmaxf(s_acc[ii][2], s_acc[ii][3]));
            #pragma unroll
            for (int off = 8; off >= 1; off >>= 1)
                mx = fmaxf(mx, __shfl_xor_sync(0xffffffffu, mx, off));
            mx *= scale;
            float m_new = fmaxf(m_r[ii], mx);
            float corr = __expf(m_r[ii] - m_new);
            float sum = 0.f;
            #pragma unroll
            for (int jj = 0; jj < 4; jj++) {
                float pv = __expf(s_acc[ii][jj] * scale - m_new);
                p[ii][jj] = pv;
                sum += pv;
            }
            #pragma unroll
            for (int off = 8; off >= 1; off >>= 1)
                sum += __shfl_xor_sync(0xffffffffu, sum, off);
            l_r[ii] = l_r[ii] * corr + sum;
            m_r[ii] = m_new;
            #pragma unroll
            for (int jj = 0; jj < 4; jj++) acc_o[ii][jj] *= corr;
        }

        // P -> smem transposed [j][i]
        #pragma unroll
        for (int jj = 0; jj < 4; jj++)
            #pragma unroll
            for (int ii = 0; ii < 4; ii++)
                KPs[tc * 4 + jj][tr * 4 + ii] = p[ii][jj];
        __syncthreads();

        // acc_o += P @ V
        #pragma unroll 8
        for (int j = 0; j < 64; j++) {
            float4 a = *(const float4*)&KPs[j][tr * 4];     // broadcast
            float4 bq = *(const float4*)&Vs[j][tc * 4];     // conflict-free
            float av[4] = {a.x, a.y, a.z, a.w};
            float bv[4] = {bq.x, bq.y, bq.z, bq.w};
            #pragma unroll
            for (int ii = 0; ii < 4; ii++)
                #pragma unroll
                for (int jj = 0; jj < 4; jj++)
                    acc_o[ii][jj] += av[ii] * bv[jj];
        }
        __syncthreads();   // before next tile overwrites KPs/Vs
    }

    // O write: row i0+tr*4+ii, cols h*64 + tc*4..+3
    #pragma unroll
    for (int ii = 0; ii < 4; ii++) {
        float inv = 1.f / l_r[ii];
        int i = i0 + tr * 4 + ii;
        float* dst = g_o + (long)(b * SS + i) * EE + h * 64 + tc * 4;
        *(float4*)dst = make_float4(acc_o[ii][0] * inv, acc_o[ii][1] * inv,
                                    acc_o[ii][2] * inv, acc_o[ii][3] * inv);
    }
}

// ---------------------------------------------------------------------------
// Kernel 3: y = LN(x + attn_out) * gamma + beta   (one block per row)
// ---------------------------------------------------------------------------
__global__ __launch_bounds__(256) void ln_kernel(
    const float* __restrict__ X,
    const float* __restrict__ gamma,
    const float* __restrict__ beta,
    float* __restrict__ out)
{
    __shared__ float ssum[8], ssq[8];
    const int row = blockIdx.x;
    const int tid = (int)threadIdx.x;
    const float* xr = X + (long)row * EE;
    const float* orow = g_o + (long)row * EE;

    float y[3];
    float sum = 0.f, sq = 0.f;
    #pragma unroll
    for (int r = 0; r < 3; r++) {
        int e = tid + 256 * r;
        float v = xr[e] + orow[e];
        y[r] = v;
        sum += v;
        sq += v * v;
    }
    #pragma unroll
    for (int off = 16; off >= 1; off >>= 1) {
        sum += __shfl_xor_sync(0xffffffffu, sum, off);
        sq  += __shfl_xor_sync(0xffffffffu, sq, off);
    }
    int warp = tid >> 5, lane = tid & 31;
    if (lane == 0) { ssum[warp] = sum; ssq[warp] = sq; }
    __syncthreads();
    if (warp == 0) {
        float s = (lane < 8) ? ssum[lane] : 0.f;
        float q = (lane < 8) ? ssq[lane] : 0.f;
        #pragma unroll
        for (int off = 4; off >= 1; off >>= 1) {
            s += __shfl_xor_sync(0xffffffffu, s, off);
            q += __shfl_xor_sync(0xffffffffu, q, off);
        }
        if (lane == 0) { ssum[0] = s; ssq[0] = q; }
    }
    __syncthreads();
    const float inv_e = 1.f / (float)EE;
    float mean = ssum[0] * inv_e;
    float var  = ssq[0] * inv_e - mean * mean;
    float rstd = rsqrtf(var + 1e-5f);
    #pragma unroll
    for (int r = 0; r < 3; r++) {
        int e = tid + 256 * r;
        out[(long)row * EE + e] = (y[r] - mean) * rstd * gamma[e] + beta[e];
    }
}

// ---------------------------------------------------------------------------
extern "C" void kernel_launch(void* const* d_in, const int* in_sizes, int n_in,
                              void* d_out, int out_size)
{
    const float* x     = (const float*)d_in[0];
    const float* w_qkv = (const float*)d_in[1];
    const float* b_qkv = (const float*)d_in[2];
    const float* gamma = (const float*)d_in[3];
    const float* beta  = (const float*)d_in[4];
    float* out = (float*)d_out;

    dim3 g1(N3 / 128, MTOT / 128);          // 18 x 64
    qkv_gemm_kernel<<<g1, 256>>>(x, w_qkv, b_qkv);

    dim3 g2(SS / 64, HH, BB);               // 16 x 12 x 8
    attn_kernel<<<g2, 256>>>();

    ln_kernel<<<MTOT, 256>>>(x, gamma, beta, out);
}

// round 8
// speedup vs baseline: 1.4132x; 1.4132x over previous
#include <cuda_runtime.h>
#include <cuda_bf16.h>
#include <cstdint>

#define BB 8
#define SS 1024
#define EE 768
#define HH 12
#define DD 64
#define MTOT (BB*SS)      // 8192
#define N3 (3*EE)         // 2304

// ------------------------- scratch (__device__ globals) ---------------------
__device__ float g_q[BB*HH*SS*DD];   // [B,H,S,D]
__device__ float g_k[BB*HH*SS*DD];
__device__ float g_v[BB*HH*SS*DD];
__device__ float g_o[BB*SS*EE];      // attention output [B,S,E]

__device__ __nv_bfloat16 g_xh[(long)MTOT*EE];  // X split hi
__device__ __nv_bfloat16 g_xl[(long)MTOT*EE];  // X split lo
__device__ __nv_bfloat16 g_wh[(long)N3*EE];    // W^T split hi  [N3][EE] (K-major)
__device__ __nv_bfloat16 g_wl[(long)N3*EE];    // W^T split lo

// ---------------------------------------------------------------------------
// Conversion kernels: fp32 -> bf16 hi/lo split (W also transposed to [N3][EE])
// ---------------------------------------------------------------------------
__global__ __launch_bounds__(256) void cvt_x_kernel(const float* __restrict__ X)
{
    long i = ((long)blockIdx.x * 256 + threadIdx.x) * 4;
    float4 v = *(const float4*)(X + i);
    float vv[4] = {v.x, v.y, v.z, v.w};
    #pragma unroll
    for (int c = 0; c < 4; c++) {
        __nv_bfloat16 h = __float2bfloat16(vv[c]);
        float lo = vv[c] - __bfloat162float(h);
        g_xh[i + c] = h;
        g_xl[i + c] = __float2bfloat16(lo);
    }
}

__global__ __launch_bounds__(256) void cvt_w_kernel(const float* __restrict__ W)
{
    __shared__ float t[32][33];
    const int n0 = blockIdx.x * 32;
    const int k0 = blockIdx.y * 32;
    const int tx = threadIdx.x & 31;
    const int ty = threadIdx.x >> 5;   // 0..7
    #pragma unroll
    for (int r = 0; r < 4; r++) {
        int k = k0 + ty + 8 * r;
        t[ty + 8 * r][tx] = W[(long)k * N3 + n0 + tx];
    }
    __syncthreads();
    #pragma unroll
    for (int r = 0; r < 4; r++) {
        int n = n0 + ty + 8 * r;
        float v = t[tx][ty + 8 * r];
        __nv_bfloat16 h = __float2bfloat16(v);
        float lo = v - __bfloat162float(h);
        g_wh[(long)n * EE + k0 + tx] = h;
        g_wl[(long)n * EE + k0 + tx] = __float2bfloat16(lo);
    }
}

// ------------------------- mma.sync helpers ---------------------------------
__device__ __forceinline__ void mma_bf16(float* c, const uint32_t* a, const uint32_t* b)
{
    asm volatile(
        "mma.sync.aligned.m16n8k16.row.col.f32.bf16.bf16.f32 "
        "{%0,%1,%2,%3}, {%4,%5,%6,%7}, {%8,%9}, {%0,%1,%2,%3};"
        : "+f"(c[0]), "+f"(c[1]), "+f"(c[2]), "+f"(c[3])
        : "r"(a[0]), "r"(a[1]), "r"(a[2]), "r"(a[3]), "r"(b[0]), "r"(b[1]));
}

// A fragment (m16k16) from SW128-swizzled [rows][64 bf16] tile.
// Matrices: (rm,k0),(rm+8,k0),(rm,k0+8),(rm+8,k0+8) -> a0..a3 operand order.
__device__ __forceinline__ void ldsm_a(uint32_t* r, uint32_t tb, int rm, int k0, int lane)
{
    int mat = lane >> 3, rr = lane & 7;
    int row = rm + rr + (mat & 1) * 8;
    int kb  = (k0 + (mat >> 1) * 8) * 2;
    uint32_t boff = (uint32_t)(row * 128 + kb);
    uint32_t addr = tb + (boff ^ ((boff >> 3) & 0x70));
    asm volatile("ldmatrix.sync.aligned.m8n8.x4.shared.b16 {%0,%1,%2,%3}, [%4];"
                 : "=r"(r[0]), "=r"(r[1]), "=r"(r[2]), "=r"(r[3]) : "r"(addr));
}

// Two B fragments (k16n8 each) for n rows nb..nb+15 from [n][64 bf16] K-major tile.
// Matrices: (nb,k0),(nb,k0+8),(nb+8,k0),(nb+8,k0+8) -> {nf0.b0, nf0.b1, nf1.b0, nf1.b1}
__device__ __forceinline__ void ldsm_b(uint32_t* r, uint32_t tb, int nb, int k0, int lane)
{
    int mat = lane >> 3, rr = lane & 7;
    int row = nb + rr + (mat >> 1) * 8;
    int kb  = (k0 + (mat & 1) * 8) * 2;
    uint32_t boff = (uint32_t)(row * 128 + kb);
    uint32_t addr = tb + (boff ^ ((boff >> 3) & 0x70));
    asm volatile("ldmatrix.sync.aligned.m8n8.x4.shared.b16 {%0,%1,%2,%3}, [%4];"
                 : "=r"(r[0]), "=r"(r[1]), "=r"(r[2]), "=r"(r[3]) : "r"(addr));
}

// ---------------------------------------------------------------------------
// Kernel 1: QKV GEMM on mma.sync bf16 (split precision, fp32 accumulate)
// CTA tile 128x128, K-chunks of 64, double-buffered cp.async stages.
// C = Xh*Wh + Xh*Wl + Xl*Wh, + bias, scatter into q/k/v [B,H,S,D].
// ---------------------------------------------------------------------------
#define TILE_BYTES  16384        // 128 rows * 128B (64 bf16 swizzled)
#define STAGE_BYTES (4*TILE_BYTES)   // Ah, Al, Bh, Bl
#define GEMM_DYN_SMEM (2*STAGE_BYTES)

__global__ __launch_bounds__(256, 1) void qkv_gemm_tc(const float* __restrict__ bias)
{
    extern __shared__ __align__(128) char smem[];
    const uint32_t sbase = (uint32_t)__cvta_generic_to_shared(smem);
    const int tid = (int)threadIdx.x;
    const int wid = tid >> 5, lid = tid & 31;
    const int n0 = blockIdx.x * 128;
    const int m0 = blockIdx.y * 128;

    const int wm = (wid & 3) * 32;      // warp M offset within tile
    const int wn = (wid >> 2) * 64;     // warp N offset within tile

    const __nv_bfloat16* __restrict__ srcs[4] = {
        g_xh + (long)m0 * EE,   // A hi (rows = m)
        g_xl + (long)m0 * EE,   // A lo
        g_wh + (long)n0 * EE,   // B hi (rows = n, K-major)
        g_wl + (long)n0 * EE }; // B lo

    // ---- cp.async stage loader: 4 tiles of [128][64 bf16], SW128 swizzle ----
    auto stage_load = [&](int chunk, int buf) {
        const int k0 = chunk * 64;
        const uint32_t dstbase = sbase + buf * STAGE_BYTES;
        #pragma unroll
        for (int t = 0; t < 4; t++) {
            const __nv_bfloat16* src = srcs[t] + k0;
            const uint32_t dtile = dstbase + t * TILE_BYTES;
            #pragma unroll
            for (int v = 0; v < 4; v++) {
                int f = tid + 256 * v;
                int row = f >> 3;
                int seg = f & 7;
                uint32_t boff = (uint32_t)(row * 128 + seg * 16);
                uint32_t sw = dtile + (boff ^ ((boff >> 3) & 0x70));
                const __nv_bfloat16* s = src + (long)row * EE + seg * 8;
                asm volatile("cp.async.cg.shared.global [%0], [%1], 16;"
                             :: "r"(sw), "l"(s) : "memory");
            }
        }
        asm volatile("cp.async.commit_group;" ::: "memory");
    };

    float acc[2][8][4];
    #pragma unroll
    for (int mf = 0; mf < 2; mf++)
        #pragma unroll
        for (int nf = 0; nf < 8; nf++)
            #pragma unroll
            for (int c = 0; c < 4; c++) acc[mf][nf][c] = 0.f;

    stage_load(0, 0);

    for (int chunk = 0; chunk < 12; chunk++) {
        const int buf = chunk & 1;
        if (chunk + 1 < 12) {
            stage_load(chunk + 1, buf ^ 1);
            asm volatile("cp.async.wait_group 1;" ::: "memory");
        } else {
            asm volatile("cp.async.wait_group 0;" ::: "memory");
        }
        __syncthreads();

        const uint32_t stg = sbase + buf * STAGE_BYTES;
        const uint32_t sAh = stg;
        const uint32_t sAl = stg + TILE_BYTES;
        const uint32_t sBh = stg + 2 * TILE_BYTES;
        const uint32_t sBl = stg + 3 * TILE_BYTES;

        #pragma unroll
        for (int ks = 0; ks < 4; ks++) {
            const int k0 = ks * 16;
            uint32_t ah[2][4], al[2][4], bh[4][4], bl[4][4];
            ldsm_a(ah[0], sAh, wm, k0, lid);
            ldsm_a(ah[1], sAh, wm + 16, k0, lid);
            ldsm_a(al[0], sAl, wm, k0, lid);
            ldsm_a(al[1], sAl, wm + 16, k0, lid);
            #pragma unroll
            for (int q = 0; q < 4; q++) {
                ldsm_b(bh[q], sBh, wn + q * 16, k0, lid);
                ldsm_b(bl[q], sBl, wn + q * 16, k0, lid);
            }
            #pragma unroll
            for (int mf = 0; mf < 2; mf++)
                #pragma unroll
                for (int nf = 0; nf < 8; nf++) {
                    const uint32_t* bhp = &bh[nf >> 1][(nf & 1) * 2];
                    const uint32_t* blp = &bl[nf >> 1][(nf & 1) * 2];
                    mma_bf16(acc[mf][nf], ah[mf], bhp);
                    mma_bf16(acc[mf][nf], ah[mf], blp);
                    mma_bf16(acc[mf][nf], al[mf], bhp);
                }
        }
        __syncthreads();
    }

    // ---- Epilogue: +bias, scatter to q/k/v [B,H,S,D] ----
    // acc fragment: c0,c1 = (row gID, col tig*2,+1); c2,c3 = (row gID+8)
    const int gID = lid >> 2, tig = lid & 3;
    const int nbase = n0 + wn;                 // multiple of 64 -> one head
    const int which = nbase / EE;              // 0=q 1=k 2=v
    float* dstb = (which == 0) ? g_q : ((which == 1) ? g_k : g_v);
    const int h = (nbase - which * EE) >> 6;

    #pragma unroll
    for (int mf = 0; mf < 2; mf++) {
        const int m = m0 + wm + mf * 16 + gID;
        const int b0_ = m >> 10,       s0_ = m & 1023;
        const int b1_ = (m + 8) >> 10, s1_ = (m + 8) & 1023;
        float* r0 = dstb + (((long)(b0_ * HH + h) * SS + s0_) * DD);
        float* r1 = dstb + (((long)(b1_ * HH + h) * SS + s1_) * DD);
        #pragma unroll
        for (int nf = 0; nf < 8; nf++) {
            const int d = nf * 8 + tig * 2;
            float2 bv = *(const float2*)&bias[nbase + d];
            float2 o0 = make_float2(acc[mf][nf][0] + bv.x, acc[mf][nf][1] + bv.y);
            float2 o1 = make_float2(acc[mf][nf][2] + bv.x, acc[mf][nf][3] + bv.y);
            *(float2*)(r0 + d) = o0;
            *(float2*)(r1 + d) = o1;
        }
    }
}

// ---------------------------------------------------------------------------
// Kernel 2: flash attention (fp32, online softmax) — unchanged
// ---------------------------------------------------------------------------
__global__ __launch_bounds__(256) void attn_kernel()
{
    __shared__ float Qs[64][64];
    __shared__ float KPs[64][64];
    __shared__ float Vs[64][64];

    const int qt = blockIdx.x;
    const int h  = blockIdx.y;
    const int b  = blockIdx.z;
    const int tid = (int)threadIdx.x;
    const int tr = tid >> 4;
    const int tc = tid & 15;

    const long bh = (long)(b * HH + h) * SS;
    const float* Q = g_q + bh * DD;
    const float* K = g_k + bh * DD;
    const float* V = g_v + bh * DD;
    const int i0 = qt * 64;

    {
        int i = tid >> 2;
        int dbase = (tid & 3) * 16;
        const float* src = Q + (long)(i0 + i) * DD + dbase;
        #pragma unroll
        for (int q = 0; q < 4; q++) {
            float4 v = *(const float4*)(src + q * 4);
            int d = dbase + q * 4;
            Qs[d + 0][i] = v.x;
            Qs[d + 1][i] = v.y;
            Qs[d + 2][i] = v.z;
            Qs[d + 3][i] = v.w;
        }
    }

    float m_r[4], l_r[4], acc_o[4][4];
    #pragma unroll
    for (int ii = 0; ii < 4; ii++) {
        m_r[ii] = -1e30f;
        l_r[ii] = 0.f;
        #pragma unroll
        for (int jj = 0; jj < 4; jj++) acc_o[ii][jj] = 0.f;
    }

    const float scale = 0.125f;

    for (int j0 = 0; j0 < SS; j0 += 64) {
        {
            int j = tid >> 2;
            int dbase = (tid & 3) * 16;
            const float* src = K + (long)(j0 + j) * DD + dbase;
            #pragma unroll
            for (int q = 0; q < 4; q++) {
                float4 v = *(const float4*)(src + q * 4);
                int d = dbase + q * 4;
                KPs[d + 0][j] = v.x;
                KPs[d + 1][j] = v.y;
                KPs[d + 2][j] = v.z;
                KPs[d + 3][j] = v.w;
            }
        }
        {
            const float* src = V + (long)j0 * DD;
            #pragma unroll
            for (int r = 0; r < 4; r++) {
                int idx = tid + 256 * r;
                int j = idx >> 4;
                int d = (idx & 15) * 4;
                *(float4*)&Vs[j][d] = *(const float4*)(src + j * DD + d);
            }
        }
        __syncthreads();

        float s_acc[4][4];
        #pragma unroll
        for (int ii = 0; ii < 4; ii++)
            #pragma unroll
            for (int jj = 0; jj < 4; jj++) s_acc[ii][jj] = 0.f;

        #pragma unroll 8
        for (int kk = 0; kk < 64; kk++) {
            float4 a = *(const float4*)&Qs[kk][tr * 4];
            float4 bq = *(const float4*)&KPs[kk][tc * 4];
            float av[4] = {a.x, a.y, a.z, a.w};
            float bv[4] = {bq.x, bq.y, bq.z, bq.w};
            #pragma unroll
            for (int ii = 0; ii < 4; ii++)
                #pragma unroll
                for (int jj = 0; jj < 4; jj++)
                    s_acc[ii][jj] += av[ii] * bv[jj];
        }
        __syncthreads();

        float p[4][4];
        #pragma unroll
        for (int ii = 0; ii < 4; ii++) {
            float mx = fmaxf(fmaxf(s_acc[ii][0], s_acc[ii][1]),
                             fmaxf(s_acc[ii][2], s_acc[ii][3]));
            #pragma unroll
            for (int off = 8; off >= 1; off >>= 1)
                mx = fmaxf(mx, __shfl_xor_sync(0xffffffffu, mx, off));
            mx *= scale;
            float m_new = fmaxf(m_r[ii], mx);
            float corr = __expf(m_r[ii] - m_new);
            float sum = 0.f;
            #pragma unroll
            for (int jj = 0; jj < 4; jj++) {
                float pv = __expf(s_acc[ii][jj] * scale - m_new);
                p[ii][jj] = pv;
                sum += pv;
            }
            #pragma unroll
            for (int off = 8; off >= 1; off >>= 1)
                sum += __shfl_xor_sync(0xffffffffu, sum, off);
            l_r[ii] = l_r[ii] * corr + sum;
            m_r[ii] = m_new;
            #pragma unroll
            for (int jj = 0; jj < 4; jj++) acc_o[ii][jj] *= corr;
        }

        #pragma unroll
        for (int jj = 0; jj < 4; jj++)
            #pragma unroll
            for (int ii = 0; ii < 4; ii++)
                KPs[tc * 4 + jj][tr * 4 + ii] = p[ii][jj];
        __syncthreads();

        #pragma unroll 8
        for (int j = 0; j < 64; j++) {
            float4 a = *(const float4*)&KPs[j][tr * 4];
            float4 bq = *(const float4*)&Vs[j][tc * 4];
            float av[4] = {a.x, a.y, a.z, a.w};
            float bv[4] = {bq.x, bq.y, bq.z, bq.w};
            #pragma unroll
            for (int ii = 0; ii < 4; ii++)
                #pragma unroll
                for (int jj = 0; jj < 4; jj++)
                    acc_o[ii][jj] += av[ii] * bv[jj];
        }
        __syncthreads();
    }

    #pragma unroll
    for (int ii = 0; ii < 4; ii++) {
        float inv = 1.f / l_r[ii];
        int i = i0 + tr * 4 + ii;
        float* dst = g_o + (long)(b * SS + i) * EE + h * 64 + tc * 4;
        *(float4*)dst = make_float4(acc_o[ii][0] * inv, acc_o[ii][1] * inv,
                                    acc_o[ii][2] * inv, acc_o[ii][3] * inv);
    }
}

// ---------------------------------------------------------------------------
// Kernel 3: y = LN(x + attn_out) * gamma + beta — unchanged
// ---------------------------------------------------------------------------
__global__ __launch_bounds__(256) void ln_kernel(
    const float* __restrict__ X,
    const float* __restrict__ gamma,
    const float* __restrict__ beta,
    float* __restrict__ out)
{
    __shared__ float ssum[8], ssq[8];
    const int row = blockIdx.x;
    const int tid = (int)threadIdx.x;
    const float* xr = X + (long)row * EE;
    const float* orow = g_o + (long)row * EE;

    float y[3];
    float sum = 0.f, sq = 0.f;
    #pragma unroll
    for (int r = 0; r < 3; r++) {
        int e = tid + 256 * r;
        float v = xr[e] + orow[e];
        y[r] = v;
        sum += v;
        sq += v * v;
    }
    #pragma unroll
    for (int off = 16; off >= 1; off >>= 1) {
        sum += __shfl_xor_sync(0xffffffffu, sum, off);
        sq  += __shfl_xor_sync(0xffffffffu, sq, off);
    }
    int warp = tid >> 5, lane = tid & 31;
    if (lane == 0) { ssum[warp] = sum; ssq[warp] = sq; }
    __syncthreads();
    if (warp == 0) {
        float s = (lane < 8) ? ssum[lane] : 0.f;
        float q = (lane < 8) ? ssq[lane] : 0.f;
        #pragma unroll
        for (int off = 4; off >= 1; off >>= 1) {
            s += __shfl_xor_sync(0xffffffffu, s, off);
            q += __shfl_xor_sync(0xffffffffu, q, off);
        }
        if (lane == 0) { ssum[0] = s; ssq[0] = q; }
    }
    __syncthreads();
    const float inv_e = 1.f / (float)EE;
    float mean = ssum[0] * inv_e;
    float var  = ssq[0] * inv_e - mean * mean;
    float rstd = rsqrtf(var + 1e-5f);
    #pragma unroll
    for (int r = 0; r < 3; r++) {
        int e = tid + 256 * r;
        out[(long)row * EE + e] = (y[r] - mean) * rstd * gamma[e] + beta[e];
    }
}

// ---------------------------------------------------------------------------
extern "C" void kernel_launch(void* const* d_in, const int* in_sizes, int n_in,
                              void* d_out, int out_size)
{
    const float* x     = (const float*)d_in[0];
    const float* w_qkv = (const float*)d_in[1];
    const float* b_qkv = (const float*)d_in[2];
    const float* gamma = (const float*)d_in[3];
    const float* beta  = (const float*)d_in[4];
    float* out = (float*)d_out;

    cudaFuncSetAttribute(qkv_gemm_tc,
                         cudaFuncAttributeMaxDynamicSharedMemorySize, GEMM_DYN_SMEM);

    cvt_x_kernel<<<(MTOT * EE) / 1024, 256>>>(x);
    cvt_w_kernel<<<dim3(N3 / 32, EE / 32), 256>>>(w_qkv);

    dim3 g1(N3 / 128, MTOT / 128);          // 18 x 64
    qkv_gemm_tc<<<g1, 256, GEMM_DYN_SMEM>>>(b_qkv);

    dim3 g2(SS / 64, HH, BB);               // 16 x 12 x 8
    attn_kernel<<<g2, 256>>>();

    ln_kernel<<<MTOT, 256>>>(x, gamma, beta, out);
}

// round 10
// speedup vs baseline: 3.0484x; 2.1572x over previous
#include <cuda_runtime.h>
#include <cuda_bf16.h>
#include <cstdint>

#define BB 8
#define SS 1024
#define EE 768
#define HH 12
#define DD 64
#define MTOT (BB*SS)      // 8192
#define N3 (3*EE)         // 2304

// ------------------------- scratch (__device__ globals) ---------------------
__device__ float g_o[BB*SS*EE];      // attention output [B,S,E] fp32

__device__ __nv_bfloat16 g_xh[(long)MTOT*EE];  // X split hi
__device__ __nv_bfloat16 g_xl[(long)MTOT*EE];  // X split lo
__device__ __nv_bfloat16 g_wh[(long)N3*EE];    // W^T split hi  [N3][EE] (K-major)
__device__ __nv_bfloat16 g_wl[(long)N3*EE];    // W^T split lo

// Q/K/V split bf16, [B,H,S,D]
__device__ __nv_bfloat16 g_qh[(long)BB*HH*SS*DD];
__device__ __nv_bfloat16 g_ql[(long)BB*HH*SS*DD];
__device__ __nv_bfloat16 g_kh[(long)BB*HH*SS*DD];
__device__ __nv_bfloat16 g_kl[(long)BB*HH*SS*DD];
__device__ __nv_bfloat16 g_vh[(long)BB*HH*SS*DD];
__device__ __nv_bfloat16 g_vl[(long)BB*HH*SS*DD];

// ---------------------------------------------------------------------------
// Conversion kernels: fp32 -> bf16 hi/lo split (W also transposed to [N3][EE])
// ---------------------------------------------------------------------------
__global__ __launch_bounds__(256) void cvt_x_kernel(const float* __restrict__ X)
{
    long i = ((long)blockIdx.x * 256 + threadIdx.x) * 4;
    float4 v = *(const float4*)(X + i);
    float vv[4] = {v.x, v.y, v.z, v.w};
    #pragma unroll
    for (int c = 0; c < 4; c++) {
        __nv_bfloat16 h = __float2bfloat16(vv[c]);
        float lo = vv[c] - __bfloat162float(h);
        g_xh[i + c] = h;
        g_xl[i + c] = __float2bfloat16(lo);
    }
}

__global__ __launch_bounds__(256) void cvt_w_kernel(const float* __restrict__ W)
{
    __shared__ float t[32][33];
    const int n0 = blockIdx.x * 32;
    const int k0 = blockIdx.y * 32;
    const int tx = threadIdx.x & 31;
    const int ty = threadIdx.x >> 5;   // 0..7
    #pragma unroll
    for (int r = 0; r < 4; r++) {
        int k = k0 + ty + 8 * r;
        t[ty + 8 * r][tx] = W[(long)k * N3 + n0 + tx];
    }
    __syncthreads();
    #pragma unroll
    for (int r = 0; r < 4; r++) {
        int n = n0 + ty + 8 * r;
        float v = t[tx][ty + 8 * r];
        __nv_bfloat16 h = __float2bfloat16(v);
        float lo = v - __bfloat162float(h);
        g_wh[(long)n * EE + k0 + tx] = h;
        g_wl[(long)n * EE + k0 + tx] = __float2bfloat16(lo);
    }
}

// ------------------------- mma.sync helpers ---------------------------------
__device__ __forceinline__ void mma_bf16(float* c, const uint32_t* a, const uint32_t* b)
{
    asm volatile(
        "mma.sync.aligned.m16n8k16.row.col.f32.bf16.bf16.f32 "
        "{%0,%1,%2,%3}, {%4,%5,%6,%7}, {%8,%9}, {%0,%1,%2,%3};"
        : "+f"(c[0]), "+f"(c[1]), "+f"(c[2]), "+f"(c[3])
        : "r"(a[0]), "r"(a[1]), "r"(a[2]), "r"(a[3]), "r"(b[0]), "r"(b[1]));
}

// A fragment (m16k16) from SW128-swizzled [rows][64 bf16] tile.
__device__ __forceinline__ void ldsm_a(uint32_t* r, uint32_t tb, int rm, int k0, int lane)
{
    int mat = lane >> 3, rr = lane & 7;
    int row = rm + rr + (mat & 1) * 8;
    int kb  = (k0 + (mat >> 1) * 8) * 2;
    uint32_t boff = (uint32_t)(row * 128 + kb);
    uint32_t addr = tb + (boff ^ ((boff >> 3) & 0x70));
    asm volatile("ldmatrix.sync.aligned.m8n8.x4.shared.b16 {%0,%1,%2,%3}, [%4];"
                 : "=r"(r[0]), "=r"(r[1]), "=r"(r[2]), "=r"(r[3]) : "r"(addr));
}

// Two B fragments (k16n8) for n rows nb..nb+15 from [n][64 bf16] K-major tile.
// frag nf even: regs {r0,r1}; odd: {r2,r3}.
__device__ __forceinline__ void ldsm_b(uint32_t* r, uint32_t tb, int nb, int k0, int lane)
{
    int mat = lane >> 3, rr = lane & 7;
    int row = nb + rr + (mat >> 1) * 8;
    int kb  = (k0 + (mat & 1) * 8) * 2;
    uint32_t boff = (uint32_t)(row * 128 + kb);
    uint32_t addr = tb + (boff ^ ((boff >> 3) & 0x70));
    asm volatile("ldmatrix.sync.aligned.m8n8.x4.shared.b16 {%0,%1,%2,%3}, [%4];"
                 : "=r"(r[0]), "=r"(r[1]), "=r"(r[2]), "=r"(r[3]) : "r"(addr));
}

// V fragments via ldmatrix.trans on row-major [j][64 d] tile (128B rows, SW128).
// Covers j0..j0+15 x d0..d0+15. After trans:
//   r0=(d0-7, j0-7)  r1=(d0-7, j8-15)  r2=(d8-15, j0-7)  r3=(d8-15, j8-15)
// B-frag for d-block d0-7: {r0,r1}; d8-15: {r2,r3}.
__device__ __forceinline__ void ldsm_v(uint32_t* r, uint32_t tb, int j0, int d0, int lane)
{
    int mat = lane >> 3, rr = lane & 7;
    int row = j0 + rr + (mat & 1) * 8;
    int db  = (d0 + (mat >> 1) * 8) * 2;
    uint32_t boff = (uint32_t)(row * 128 + db);
    uint32_t addr = tb + (boff ^ ((boff >> 3) & 0x70));
    asm volatile("ldmatrix.sync.aligned.m8n8.x4.trans.shared.b16 {%0,%1,%2,%3}, [%4];"
                 : "=r"(r[0]), "=r"(r[1]), "=r"(r[2]), "=r"(r[3]) : "r"(addr));
}

__device__ __forceinline__ uint32_t pack_bf16(float a, float b)
{
    __nv_bfloat16 x = __float2bfloat16(a), y = __float2bfloat16(b);
    return ((uint32_t)__bfloat16_as_ushort(y) << 16) | (uint32_t)__bfloat16_as_ushort(x);
}

// ---------------------------------------------------------------------------
// Kernel 1: QKV GEMM on mma.sync bf16 (split precision, fp32 accumulate)
// Epilogue: +bias, split to bf16 hi/lo, scatter into q/k/v [B,H,S,D].
// ---------------------------------------------------------------------------
#define TILE_BYTES  16384            // 128 rows * 128B (64 bf16 swizzled)
#define STAGE_BYTES (4*TILE_BYTES)   // Ah, Al, Bh, Bl
#define GEMM_DYN_SMEM (2*STAGE_BYTES)

__global__ __launch_bounds__(256, 1) void qkv_gemm_tc(const float* __restrict__ bias)
{
    extern __shared__ __align__(128) char smem[];
    const uint32_t sbase = (uint32_t)__cvta_generic_to_shared(smem);
    const int tid = (int)threadIdx.x;
    const int wid = tid >> 5, lid = tid & 31;
    const int n0 = blockIdx.x * 128;
    const int m0 = blockIdx.y * 128;

    const int wm = (wid & 3) * 32;
    const int wn = (wid >> 2) * 64;

    const __nv_bfloat16* __restrict__ srcs[4] = {
        g_xh + (long)m0 * EE,
        g_xl + (long)m0 * EE,
        g_wh + (long)n0 * EE,
        g_wl + (long)n0 * EE };

    auto stage_load = [&](int chunk, int buf) {
        const int k0 = chunk * 64;
        const uint32_t dstbase = sbase + buf * STAGE_BYTES;
        #pragma unroll
        for (int t = 0; t < 4; t++) {
            const __nv_bfloat16* src = srcs[t] + k0;
            const uint32_t dtile = dstbase + t * TILE_BYTES;
            #pragma unroll
            for (int v = 0; v < 4; v++) {
                int f = tid + 256 * v;
                int row = f >> 3;
                int seg = f & 7;
                uint32_t boff = (uint32_t)(row * 128 + seg * 16);
                uint32_t sw = dtile + (boff ^ ((boff >> 3) & 0x70));
                const __nv_bfloat16* s = src + (long)row * EE + seg * 8;
                asm volatile("cp.async.cg.shared.global [%0], [%1], 16;"
                             :: "r"(sw), "l"(s) : "memory");
            }
        }
        asm volatile("cp.async.commit_group;" ::: "memory");
    };

    float acc[2][8][4];
    #pragma unroll
    for (int mf = 0; mf < 2; mf++)
        #pragma unroll
        for (int nf = 0; nf < 8; nf++)
            #pragma unroll
            for (int c = 0; c < 4; c++) acc[mf][nf][c] = 0.f;

    stage_load(0, 0);

    for (int chunk = 0; chunk < 12; chunk++) {
        const int buf = chunk & 1;
        if (chunk + 1 < 12) {
            stage_load(chunk + 1, buf ^ 1);
            asm volatile("cp.async.wait_group 1;" ::: "memory");
        } else {
            asm volatile("cp.async.wait_group 0;" ::: "memory");
        }
        __syncthreads();

        const uint32_t stg = sbase + buf * STAGE_BYTES;
        const uint32_t sAh = stg;
        const uint32_t sAl = stg + TILE_BYTES;
        const uint32_t sBh = stg + 2 * TILE_BYTES;
        const uint32_t sBl = stg + 3 * TILE_BYTES;

        #pragma unroll
        for (int ks = 0; ks < 4; ks++) {
            const int k0 = ks * 16;
            uint32_t ah[2][4], al[2][4], bh[4][4], bl[4][4];
            ldsm_a(ah[0], sAh, wm, k0, lid);
            ldsm_a(ah[1], sAh, wm + 16, k0, lid);
            ldsm_a(al[0], sAl, wm, k0, lid);
            ldsm_a(al[1], sAl, wm + 16, k0, lid);
            #pragma unroll
            for (int q = 0; q < 4; q++) {
                ldsm_b(bh[q], sBh, wn + q * 16, k0, lid);
                ldsm_b(bl[q], sBl, wn + q * 16, k0, lid);
            }
            #pragma unroll
            for (int mf = 0; mf < 2; mf++)
                #pragma unroll
                for (int nf = 0; nf < 8; nf++) {
                    const uint32_t* bhp = &bh[nf >> 1][(nf & 1) * 2];
                    const uint32_t* blp = &bl[nf >> 1][(nf & 1) * 2];
                    mma_bf16(acc[mf][nf], ah[mf], bhp);
                    mma_bf16(acc[mf][nf], ah[mf], blp);
                    mma_bf16(acc[mf][nf], al[mf], bhp);
                }
        }
        __syncthreads();
    }

    // ---- Epilogue: +bias, split hi/lo, scatter to q/k/v [B,H,S,D] bf16 ----
    const int gID = lid >> 2, tig = lid & 3;
    const int nbase = n0 + wn;                 // multiple of 64 -> one head
    const int which = nbase / EE;              // 0=q 1=k 2=v
    __nv_bfloat16* dh = (which == 0) ? g_qh : ((which == 1) ? g_kh : g_vh);
    __nv_bfloat16* dl = (which == 0) ? g_ql : ((which == 1) ? g_kl : g_vl);
    const int h = (nbase - which * EE) >> 6;

    #pragma unroll
    for (int mf = 0; mf < 2; mf++) {
        const int m = m0 + wm + mf * 16 + gID;
        const int b0_ = m >> 10,       s0_ = m & 1023;
        const int b1_ = (m + 8) >> 10, s1_ = (m + 8) & 1023;
        const long i0 = ((long)(b0_ * HH + h) * SS + s0_) * DD;
        const long i1 = ((long)(b1_ * HH + h) * SS + s1_) * DD;
        #pragma unroll
        for (int nf = 0; nf < 8; nf++) {
            const int d = nf * 8 + tig * 2;
            float2 bv = *(const float2*)&bias[nbase + d];
            float a0 = acc[mf][nf][0] + bv.x, a1 = acc[mf][nf][1] + bv.y;
            float a2 = acc[mf][nf][2] + bv.x, a3 = acc[mf][nf][3] + bv.y;
            uint32_t h0 = pack_bf16(a0, a1);
            uint32_t h1 = pack_bf16(a2, a3);
            uint32_t l0 = pack_bf16(a0 - __bfloat162float(__ushort_as_bfloat16((unsigned short)h0)),
                                    a1 - __bfloat162float(__ushort_as_bfloat16((unsigned short)(h0 >> 16))));
            uint32_t l1 = pack_bf16(a2 - __bfloat162float(__ushort_as_bfloat16((unsigned short)h1)),
                                    a3 - __bfloat162float(__ushort_as_bfloat16((unsigned short)(h1 >> 16))));
            *(uint32_t*)(dh + i0 + d) = h0;
            *(uint32_t*)(dl + i0 + d) = l0;
            *(uint32_t*)(dh + i1 + d) = h1;
            *(uint32_t*)(dl + i1 + d) = l1;
        }
    }
}

// ---------------------------------------------------------------------------
// Kernel 2: flash attention on mma.sync bf16 (split precision).
// CTA = 128 queries x one (b,h); 16 key-chunks of 64, double-buffered cp.async.
// Warp owns 16 query rows; softmax stats within lane-quads.
// ---------------------------------------------------------------------------
#define KV_TILE   8192                 // 64 rows * 128B
#define KV_STAGE  (4*KV_TILE)          // Kh, Kl, Vh, Vl
#define ATT_QH    0
#define ATT_QL    16384
#define ATT_STG   32768
#define ATT_DYN   (32768 + 2*KV_STAGE) // 98304

__global__ __launch_bounds__(256, 2) void attn_tc()
{
    extern __shared__ __align__(128) char smem[];
    const uint32_t sbase = (uint32_t)__cvta_generic_to_shared(smem);
    const int tid = (int)threadIdx.x;
    const int wid = tid >> 5, lid = tid & 31;
    const int gID = lid >> 2, tig = lid & 3;
    const int qt = blockIdx.x;       // 0..7
    const int h  = blockIdx.y;
    const int b  = blockIdx.z;
    const int wm = wid * 16;         // warp's query rows within 128-tile

    const long bhoff = (long)(b * HH + h) * SS * DD;
    const __nv_bfloat16* Qh = g_qh + bhoff + (long)qt * 128 * DD;
    const __nv_bfloat16* Ql = g_ql + bhoff + (long)qt * 128 * DD;
    const __nv_bfloat16* srcs[4] = { g_kh + bhoff, g_kl + bhoff,
                                     g_vh + bhoff, g_vl + bhoff };

    // Q tiles (hi, lo): 128 rows x 8 segs, one cp.async group
    #pragma unroll
    for (int v = 0; v < 4; v++) {
        int f = tid + 256 * v;
        int row = f >> 3, seg = f & 7;
        uint32_t boff = (uint32_t)(row * 128 + seg * 16);
        uint32_t sw = boff ^ ((boff >> 3) & 0x70);
        const __nv_bfloat16* s0 = Qh + (long)row * DD + seg * 8;
        const __nv_bfloat16* s1 = Ql + (long)row * DD + seg * 8;
        asm volatile("cp.async.cg.shared.global [%0], [%1], 16;"
                     :: "r"(sbase + ATT_QH + sw), "l"(s0) : "memory");
        asm volatile("cp.async.cg.shared.global [%0], [%1], 16;"
                     :: "r"(sbase + ATT_QL + sw), "l"(s1) : "memory");
    }
    asm volatile("cp.async.commit_group;" ::: "memory");

    auto stage_kv = [&](int c, int buf) {
        const uint32_t dst = sbase + ATT_STG + buf * KV_STAGE;
        const long j0 = (long)c * 64;
        #pragma unroll
        for (int t = 0; t < 4; t++) {
            const __nv_bfloat16* src = srcs[t] + j0 * DD;
            #pragma unroll
            for (int v = 0; v < 2; v++) {
                int f = tid + 256 * v;
                int row = f >> 3, seg = f & 7;
                uint32_t boff = (uint32_t)(row * 128 + seg * 16);
                uint32_t sw = dst + t * KV_TILE + (boff ^ ((boff >> 3) & 0x70));
                const __nv_bfloat16* s = src + (long)row * DD + seg * 8;
                asm volatile("cp.async.cg.shared.global [%0], [%1], 16;"
                             :: "r"(sw), "l"(s) : "memory");
            }
        }
        asm volatile("cp.async.commit_group;" ::: "memory");
    };

    stage_kv(0, 0);

    float m0r = -1e30f, m1r = -1e30f, l0s = 0.f, l1s = 0.f;
    float oacc[8][4];
    #pragma unroll
    for (int nf = 0; nf < 8; nf++)
        #pragma unroll
        for (int c = 0; c < 4; c++) oacc[nf][c] = 0.f;

    const float scale = 0.125f;

    for (int c = 0; c < 16; c++) {
        const int buf = c & 1;
        if (c + 1 < 16) {
            stage_kv(c + 1, buf ^ 1);
            asm volatile("cp.async.wait_group 1;" ::: "memory");
        } else {
            asm volatile("cp.async.wait_group 0;" ::: "memory");
        }
        __syncthreads();

        const uint32_t stg = sbase + ATT_STG + buf * KV_STAGE;
        const uint32_t sKh = stg;
        const uint32_t sKl = stg + KV_TILE;
        const uint32_t sVh = stg + 2 * KV_TILE;
        const uint32_t sVl = stg + 3 * KV_TILE;

        // ---- S = Q K^T (split, raw scores in fp32) ----
        float sacc[8][4];
        #pragma unroll
        for (int nf = 0; nf < 8; nf++)
            #pragma unroll
            for (int cc = 0; cc < 4; cc++) sacc[nf][cc] = 0.f;

        #pragma unroll
        for (int ks = 0; ks < 4; ks++) {
            const int k0 = ks * 16;
            uint32_t ah[4], al[4];
            ldsm_a(ah, sbase + ATT_QH, wm, k0, lid);
            ldsm_a(al, sbase + ATT_QL, wm, k0, lid);
            #pragma unroll
            for (int q = 0; q < 4; q++) {
                uint32_t bh[4], bl[4];
                ldsm_b(bh, sKh, q * 16, k0, lid);
                ldsm_b(bl, sKl, q * 16, k0, lid);
                mma_bf16(sacc[2 * q],     ah, &bh[0]);
                mma_bf16(sacc[2 * q],     ah, &bl[0]);
                mma_bf16(sacc[2 * q],     al, &bh[0]);
                mma_bf16(sacc[2 * q + 1], ah, &bh[2]);
                mma_bf16(sacc[2 * q + 1], ah, &bl[2]);
                mma_bf16(sacc[2 * q + 1], al, &bh[2]);
            }
        }

        // ---- online softmax (rows gID and gID+8 per lane) ----
        float mx0 = -1e30f, mx1 = -1e30f;
        #pragma unroll
        for (int nf = 0; nf < 8; nf++) {
            mx0 = fmaxf(mx0, fmaxf(sacc[nf][0], sacc[nf][1]));
            mx1 = fmaxf(mx1, fmaxf(sacc[nf][2], sacc[nf][3]));
        }
        #pragma unroll
        for (int off = 1; off <= 2; off <<= 1) {
            mx0 = fmaxf(mx0, __shfl_xor_sync(0xffffffffu, mx0, off));
            mx1 = fmaxf(mx1, __shfl_xor_sync(0xffffffffu, mx1, off));
        }
        float mn0 = fmaxf(m0r, mx0 * scale);
        float mn1 = fmaxf(m1r, mx1 * scale);
        float corr0 = __expf(m0r - mn0);
        float corr1 = __expf(m1r - mn1);
        float s0 = 0.f, s1 = 0.f;
        #pragma unroll
        for (int nf = 0; nf < 8; nf++) {
            float p0 = __expf(sacc[nf][0] * scale - mn0);
            float p1 = __expf(sacc[nf][1] * scale - mn0);
            float p2 = __expf(sacc[nf][2] * scale - mn1);
            float p3 = __expf(sacc[nf][3] * scale - mn1);
            sacc[nf][0] = p0; sacc[nf][1] = p1;
            sacc[nf][2] = p2; sacc[nf][3] = p3;
            s0 += p0 + p1; s1 += p2 + p3;
        }
        #pragma unroll
        for (int off = 1; off <= 2; off <<= 1) {
            s0 += __shfl_xor_sync(0xffffffffu, s0, off);
            s1 += __shfl_xor_sync(0xffffffffu, s1, off);
        }
        l0s = l0s * corr0 + s0;  m0r = mn0;
        l1s = l1s * corr1 + s1;  m1r = mn1;
        #pragma unroll
        for (int nf = 0; nf < 8; nf++) {
            oacc[nf][0] *= corr0; oacc[nf][1] *= corr0;
            oacc[nf][2] *= corr1; oacc[nf][3] *= corr1;
        }

        // ---- O += P V (P split in registers, V via ldmatrix.trans) ----
        #pragma unroll
        for (int kf = 0; kf < 4; kf++) {
            uint32_t pah[4], pal[4];
            {
                const float* f0 = sacc[2 * kf];
                const float* f1 = sacc[2 * kf + 1];
                pah[0] = pack_bf16(f0[0], f0[1]);
                pah[1] = pack_bf16(f0[2], f0[3]);
                pah[2] = pack_bf16(f1[0], f1[1]);
                pah[3] = pack_bf16(f1[2], f1[3]);
                pal[0] = pack_bf16(
                    f0[0] - __bfloat162float(__ushort_as_bfloat16((unsigned short)pah[0])),
                    f0[1] - __bfloat162float(__ushort_as_bfloat16((unsigned short)(pah[0] >> 16))));
                pal[1] = pack_bf16(
                    f0[2] - __bfloat162float(__ushort_as_bfloat16((unsigned short)pah[1])),
                    f0[3] - __bfloat162float(__ushort_as_bfloat16((unsigned short)(pah[1] >> 16))));
                pal[2] = pack_bf16(
                    f1[0] - __bfloat162float(__ushort_as_bfloat16((unsigned short)pah[2])),
                    f1[1] - __bfloat162float(__ushort_as_bfloat16((unsigned short)(pah[2] >> 16))));
                pal[3] = pack_bf16(
                    f1[2] - __bfloat162float(__ushort_as_bfloat16((unsigned short)pah[3])),
                    f1[3] - __bfloat162float(__ushort_as_bfloat16((unsigned short)(pah[3] >> 16))));
            }
            #pragma unroll
            for (int q = 0; q < 4; q++) {
                uint32_t vh[4], vl[4];
                ldsm_v(vh, sVh, kf * 16, q * 16, lid);
                ldsm_v(vl, sVl, kf * 16, q * 16, lid);
                mma_bf16(oacc[2 * q],     pah, &vh[0]);
                mma_bf16(oacc[2 * q],     pah, &vl[0]);
                mma_bf16(oacc[2 * q],     pal, &vh[0]);
                mma_bf16(oacc[2 * q + 1], pah, &vh[2]);
                mma_bf16(oacc[2 * q + 1], pah, &vl[2]);
                mma_bf16(oacc[2 * q + 1], pal, &vh[2]);
            }
        }
        __syncthreads();
    }

    // ---- normalize + write O fp32 [B,S,E] ----
    const float inv0 = 1.f / l0s, inv1 = 1.f / l1s;
    const int i0g = qt * 128 + wm + gID;
    const int i1g = i0g + 8;
    #pragma unroll
    for (int nf = 0; nf < 8; nf++) {
        const int d = h * 64 + nf * 8 + tig * 2;
        float* p0 = g_o + (long)(b * SS + i0g) * EE + d;
        float* p1 = g_o + (long)(b * SS + i1g) * EE + d;
        *(float2*)p0 = make_float2(oacc[nf][0] * inv0, oacc[nf][1] * inv0);
        *(float2*)p1 = make_float2(oacc[nf][2] * inv1, oacc[nf][3] * inv1);
    }
}

// ---------------------------------------------------------------------------
// Kernel 3: y = LN(x + attn_out) * gamma + beta — unchanged
// ---------------------------------------------------------------------------
__global__ __launch_bounds__(256) void ln_kernel(
    const float* __restrict__ X,
    const float* __restrict__ gamma,
    const float* __restrict__ beta,
    float* __restrict__ out)
{
    __shared__ float ssum[8], ssq[8];
    const int row = blockIdx.x;
    const int tid = (int)threadIdx.x;
    const float* xr = X + (long)row * EE;
    const float* orow = g_o + (long)row * EE;

    float y[3];
    float sum = 0.f, sq = 0.f;
    #pragma unroll
    for (int r = 0; r < 3; r++) {
        int e = tid + 256 * r;
        float v = xr[e] + orow[e];
        y[r] = v;
        sum += v;
        sq += v * v;
    }
    #pragma unroll
    for (int off = 16; off >= 1; off >>= 1) {
        sum += __shfl_xor_sync(0xffffffffu, sum, off);
        sq  += __shfl_xor_sync(0xffffffffu, sq, off);
    }
    int warp = tid >> 5, lane = tid & 31;
    if (lane == 0) { ssum[warp] = sum; ssq[warp] = sq; }
    __syncthreads();
    if (warp == 0) {
        float s = (lane < 8) ? ssum[lane] : 0.f;
        float q = (lane < 8) ? ssq[lane] : 0.f;
        #pragma unroll
        for (int off = 4; off >= 1; off >>= 1) {
            s += __shfl_xor_sync(0xffffffffu, s, off);
            q += __shfl_xor_sync(0xffffffffu, q, off);
        }
        if (lane == 0) { ssum[0] = s; ssq[0] = q; }
    }
    __syncthreads();
    const float inv_e = 1.f / (float)EE;
    float mean = ssum[0] * inv_e;
    float var  = ssq[0] * inv_e - mean * mean;
    float rstd = rsqrtf(var + 1e-5f);
    #pragma unroll
    for (int r = 0; r < 3; r++) {
        int e = tid + 256 * r;
        out[(long)row * EE + e] = (y[r] - mean) * rstd * gamma[e] + beta[e];
    }
}

// ---------------------------------------------------------------------------
extern "C" void kernel_launch(void* const* d_in, const int* in_sizes, int n_in,
                              void* d_out, int out_size)
{
    const float* x     = (const float*)d_in[0];
    const float* w_qkv = (const float*)d_in[1];
    const float* b_qkv = (const float*)d_in[2];
    const float* gamma = (const float*)d_in[3];
    const float* beta  = (const float*)d_in[4];
    float* out = (float*)d_out;

    cudaFuncSetAttribute(qkv_gemm_tc,
                         cudaFuncAttributeMaxDynamicSharedMemorySize, GEMM_DYN_SMEM);
    cudaFuncSetAttribute(attn_tc,
                         cudaFuncAttributeMaxDynamicSharedMemorySize, ATT_DYN);

    cvt_x_kernel<<<(MTOT * EE) / 1024, 256>>>(x);
    cvt_w_kernel<<<dim3(N3 / 32, EE / 32), 256>>>(w_qkv);

    dim3 g1(N3 / 128, MTOT / 128);          // 18 x 64
    qkv_gemm_tc<<<g1, 256, GEMM_DYN_SMEM>>>(b_qkv);

    dim3 g2(SS / 128, HH, BB);              // 8 x 12 x 8
    attn_tc<<<g2, 256, ATT_DYN>>>();

    ln_kernel<<<MTOT, 256>>>(x, gamma, beta, out);
}

// round 11
// speedup vs baseline: 4.7428x; 1.5558x over previous
#include <cuda_runtime.h>
#include <cuda_fp16.h>
#include <cstdint>

#define BB 8
#define SS 1024
#define EE 768
#define HH 12
#define DD 64
#define MTOT (BB*SS)      // 8192
#define N3 (3*EE)         // 2304

// 0.125 * log2(e): folded into Q so softmax runs in log2 domain
#define QSCALE 0.18033688011112042f

// ------------------------- scratch (__device__ globals) ---------------------
__device__ float g_o[BB*SS*EE];      // attention output [B,S,E] fp32

__device__ __half g_xh[(long)MTOT*EE];  // X fp16 (hi only)
__device__ __half g_wh[(long)N3*EE];    // W^T split hi  [N3][EE] (K-major)
__device__ __half g_wl[(long)N3*EE];    // W^T split lo

// Q/K/V fp16, [B,H,S,D].  Q pre-scaled by QSCALE, split hi/lo. K hi only. V hi/lo.
__device__ __half g_qh[(long)BB*HH*SS*DD];
__device__ __half g_ql[(long)BB*HH*SS*DD];
__device__ __half g_kh[(long)BB*HH*SS*DD];
__device__ __half g_vh[(long)BB*HH*SS*DD];
__device__ __half g_vl[(long)BB*HH*SS*DD];

// ---------------------------------------------------------------------------
// Conversion kernels
// ---------------------------------------------------------------------------
__global__ __launch_bounds__(256) void cvt_x_kernel(const float* __restrict__ X)
{
    long i = ((long)blockIdx.x * 256 + threadIdx.x) * 4;
    float4 v = *(const float4*)(X + i);
    __half2 a = __floats2half2_rn(v.x, v.y);
    __half2 b = __floats2half2_rn(v.z, v.w);
    *(__half2*)(g_xh + i)     = a;
    *(__half2*)(g_xh + i + 2) = b;
}

__global__ __launch_bounds__(256) void cvt_w_kernel(const float* __restrict__ W)
{
    __shared__ float t[32][33];
    const int n0 = blockIdx.x * 32;
    const int k0 = blockIdx.y * 32;
    const int tx = threadIdx.x & 31;
    const int ty = threadIdx.x >> 5;   // 0..7
    #pragma unroll
    for (int r = 0; r < 4; r++) {
        int k = k0 + ty + 8 * r;
        t[ty + 8 * r][tx] = W[(long)k * N3 + n0 + tx];
    }
    __syncthreads();
    #pragma unroll
    for (int r = 0; r < 4; r++) {
        int n = n0 + ty + 8 * r;
        float v = t[tx][ty + 8 * r];
        __half h = __float2half_rn(v);
        g_wh[(long)n * EE + k0 + tx] = h;
        g_wl[(long)n * EE + k0 + tx] = __float2half_rn(v - __half2float(h));
    }
}

// ------------------------- mma.sync helpers ---------------------------------
__device__ __forceinline__ void mma_f16(float* c, const uint32_t* a, const uint32_t* b)
{
    asm volatile(
        "mma.sync.aligned.m16n8k16.row.col.f32.f16.f16.f32 "
        "{%0,%1,%2,%3}, {%4,%5,%6,%7}, {%8,%9}, {%0,%1,%2,%3};"
        : "+f"(c[0]), "+f"(c[1]), "+f"(c[2]), "+f"(c[3])
        : "r"(a[0]), "r"(a[1]), "r"(a[2]), "r"(a[3]), "r"(b[0]), "r"(b[1]));
}

// A fragment (m16k16) from SW128-swizzled [rows][64 f16] tile.
__device__ __forceinline__ void ldsm_a(uint32_t* r, uint32_t tb, int rm, int k0, int lane)
{
    int mat = lane >> 3, rr = lane & 7;
    int row = rm + rr + (mat & 1) * 8;
    int kb  = (k0 + (mat >> 1) * 8) * 2;
    uint32_t boff = (uint32_t)(row * 128 + kb);
    uint32_t addr = tb + (boff ^ ((boff >> 3) & 0x70));
    asm volatile("ldmatrix.sync.aligned.m8n8.x4.shared.b16 {%0,%1,%2,%3}, [%4];"
                 : "=r"(r[0]), "=r"(r[1]), "=r"(r[2]), "=r"(r[3]) : "r"(addr));
}

// Two B fragments (k16n8) for n rows nb..nb+15 from [n][64 f16] K-major tile.
// frag even: {r0,r1}; odd: {r2,r3}.
__device__ __forceinline__ void ldsm_b(uint32_t* r, uint32_t tb, int nb, int k0, int lane)
{
    int mat = lane >> 3, rr = lane & 7;
    int row = nb + rr + (mat >> 1) * 8;
    int kb  = (k0 + (mat & 1) * 8) * 2;
    uint32_t boff = (uint32_t)(row * 128 + kb);
    uint32_t addr = tb + (boff ^ ((boff >> 3) & 0x70));
    asm volatile("ldmatrix.sync.aligned.m8n8.x4.shared.b16 {%0,%1,%2,%3}, [%4];"
                 : "=r"(r[0]), "=r"(r[1]), "=r"(r[2]), "=r"(r[3]) : "r"(addr));
}

// V fragments via ldmatrix.trans on row-major [j][64 d] tile (128B rows, SW128).
__device__ __forceinline__ void ldsm_v(uint32_t* r, uint32_t tb, int j0, int d0, int lane)
{
    int mat = lane >> 3, rr = lane & 7;
    int row = j0 + rr + (mat & 1) * 8;
    int db  = (d0 + (mat >> 1) * 8) * 2;
    uint32_t boff = (uint32_t)(row * 128 + db);
    uint32_t addr = tb + (boff ^ ((boff >> 3) & 0x70));
    asm volatile("ldmatrix.sync.aligned.m8n8.x4.trans.shared.b16 {%0,%1,%2,%3}, [%4];"
                 : "=r"(r[0]), "=r"(r[1]), "=r"(r[2]), "=r"(r[3]) : "r"(addr));
}

__device__ __forceinline__ uint32_t pack_f16(float lo, float hi)
{
    uint32_t u;
    asm("cvt.rn.f16x2.f32 %0, %1, %2;" : "=r"(u) : "f"(hi), "f"(lo));
    return u;
}

__device__ __forceinline__ float ex2f(float x)
{
    float y;
    asm("ex2.approx.f32 %0, %1;" : "=f"(y) : "f"(x));
    return y;
}

// ---------------------------------------------------------------------------
// Kernel 1: QKV GEMM, fp16 mma.sync: C = Xh*(Wh+Wl) + bias.
// Epilogue: Q -> *QSCALE, split hi/lo; K -> hi; V -> split hi/lo. [B,H,S,D].
// ---------------------------------------------------------------------------
#define QTILE_BYTES 16384            // 128 rows * 128B (64 f16 swizzled)
#define QSTAGE (3*QTILE_BYTES)       // Ah, Bh, Bl
#define GEMM_DYN_SMEM (2*QSTAGE)     // 98304

__global__ __launch_bounds__(256, 2) void qkv_gemm_tc(const float* __restrict__ bias)
{
    extern __shared__ __align__(128) char smem[];
    const uint32_t sbase = (uint32_t)__cvta_generic_to_shared(smem);
    const int tid = (int)threadIdx.x;
    const int wid = tid >> 5, lid = tid & 31;
    const int n0 = blockIdx.x * 128;
    const int m0 = blockIdx.y * 128;

    const int wm = (wid & 3) * 32;
    const int wn = (wid >> 2) * 64;

    const __half* __restrict__ srcs[3] = {
        g_xh + (long)m0 * EE,
        g_wh + (long)n0 * EE,
        g_wl + (long)n0 * EE };

    auto stage_load = [&](int chunk, int buf) {
        const int k0 = chunk * 64;
        const uint32_t dstbase = sbase + buf * QSTAGE;
        #pragma unroll
        for (int t = 0; t < 3; t++) {
            const __half* src = srcs[t] + k0;
            const uint32_t dtile = dstbase + t * QTILE_BYTES;
            #pragma unroll
            for (int v = 0; v < 4; v++) {
                int f = tid + 256 * v;
                int row = f >> 3;
                int seg = f & 7;
                uint32_t boff = (uint32_t)(row * 128 + seg * 16);
                uint32_t sw = dtile + (boff ^ ((boff >> 3) & 0x70));
                const __half* s = src + (long)row * EE + seg * 8;
                asm volatile("cp.async.cg.shared.global [%0], [%1], 16;"
                             :: "r"(sw), "l"(s) : "memory");
            }
        }
        asm volatile("cp.async.commit_group;" ::: "memory");
    };

    float acc[2][8][4];
    #pragma unroll
    for (int mf = 0; mf < 2; mf++)
        #pragma unroll
        for (int nf = 0; nf < 8; nf++)
            #pragma unroll
            for (int c = 0; c < 4; c++) acc[mf][nf][c] = 0.f;

    stage_load(0, 0);

    for (int chunk = 0; chunk < 12; chunk++) {
        const int buf = chunk & 1;
        if (chunk + 1 < 12) {
            stage_load(chunk + 1, buf ^ 1);
            asm volatile("cp.async.wait_group 1;" ::: "memory");
        } else {
            asm volatile("cp.async.wait_group 0;" ::: "memory");
        }
        __syncthreads();

        const uint32_t stg = sbase + buf * QSTAGE;
        const uint32_t sAh = stg;
        const uint32_t sBh = stg + QTILE_BYTES;
        const uint32_t sBl = stg + 2 * QTILE_BYTES;

        #pragma unroll
        for (int ks = 0; ks < 4; ks++) {
            const int k0 = ks * 16;
            uint32_t ah[2][4], bh[4][4], bl[4][4];
            ldsm_a(ah[0], sAh, wm, k0, lid);
            ldsm_a(ah[1], sAh, wm + 16, k0, lid);
            #pragma unroll
            for (int q = 0; q < 4; q++) {
                ldsm_b(bh[q], sBh, wn + q * 16, k0, lid);
                ldsm_b(bl[q], sBl, wn + q * 16, k0, lid);
            }
            #pragma unroll
            for (int mf = 0; mf < 2; mf++)
                #pragma unroll
                for (int nf = 0; nf < 8; nf++) {
                    mma_f16(acc[mf][nf], ah[mf], &bh[nf >> 1][(nf & 1) * 2]);
                    mma_f16(acc[mf][nf], ah[mf], &bl[nf >> 1][(nf & 1) * 2]);
                }
        }
        __syncthreads();
    }

    // ---- Epilogue: +bias, per-output formatting, scatter [B,H,S,D] ----
    const int gID = lid >> 2, tig = lid & 3;
    const int nbase = n0 + wn;                 // multiple of 64 -> one head
    const int which = nbase / EE;              // 0=q 1=k 2=v
    const int h = (nbase - which * EE) >> 6;

    __half* dh = (which == 0) ? g_qh : ((which == 1) ? g_kh : g_vh);
    __half* dl = (which == 0) ? g_ql : g_vl;   // unused for K
    const bool write_lo = (which != 1);
    const float sc = (which == 0) ? QSCALE : 1.f;

    #pragma unroll
    for (int mf = 0; mf < 2; mf++) {
        const int m = m0 + wm + mf * 16 + gID;
        const int b0_ = m >> 10,       s0_ = m & 1023;
        const int b1_ = (m + 8) >> 10, s1_ = (m + 8) & 1023;
        const long i0 = ((long)(b0_ * HH + h) * SS + s0_) * DD;
        const long i1 = ((long)(b1_ * HH + h) * SS + s1_) * DD;
        #pragma unroll
        for (int nf = 0; nf < 8; nf++) {
            const int d = nf * 8 + tig * 2;
            float2 bv = *(const float2*)&bias[nbase + d];
            float a0 = (acc[mf][nf][0] + bv.x) * sc;
            float a1 = (acc[mf][nf][1] + bv.y) * sc;
            float a2 = (acc[mf][nf][2] + bv.x) * sc;
            float a3 = (acc[mf][nf][3] + bv.y) * sc;
            uint32_t h0 = pack_f16(a0, a1);
            uint32_t h1 = pack_f16(a2, a3);
            *(uint32_t*)(dh + i0 + d) = h0;
            *(uint32_t*)(dh + i1 + d) = h1;
            if (write_lo) {
                __half2 hh0 = *(__half2*)&h0;
                __half2 hh1 = *(__half2*)&h1;
                uint32_t l0 = pack_f16(a0 - __half2float(hh0.x), a1 - __half2float(hh0.y));
                uint32_t l1 = pack_f16(a2 - __half2float(hh1.x), a3 - __half2float(hh1.y));
                *(uint32_t*)(dl + i0 + d) = l0;
                *(uint32_t*)(dl + i1 + d) = l1;
            }
        }
    }
}

// ---------------------------------------------------------------------------
// Kernel 2: flash attention, fp16 mma.sync.
// S = (Qh+Ql)*Kh (log2 domain, Q pre-scaled); O += Ph*(Vh+Vl).
// CTA = 128 queries x one (b,h); 16 KV chunks of 64, double-buffered cp.async.
// ---------------------------------------------------------------------------
#define KV_TILE   8192                 // 64 rows * 128B
#define KV_STAGE  (3*KV_TILE)          // Kh, Vh, Vl
#define ATT_QH    0
#define ATT_QL    16384
#define ATT_STG   32768
#define ATT_DYN   (32768 + 2*KV_STAGE) // 81920

__global__ __launch_bounds__(256, 2) void attn_tc()
{
    extern __shared__ __align__(128) char smem[];
    const uint32_t sbase = (uint32_t)__cvta_generic_to_shared(smem);
    const int tid = (int)threadIdx.x;
    const int wid = tid >> 5, lid = tid & 31;
    const int gID = lid >> 2, tig = lid & 3;
    const int qt = blockIdx.x;       // 0..7
    const int h  = blockIdx.y;
    const int b  = blockIdx.z;
    const int wm = wid * 16;

    const long bhoff = (long)(b * HH + h) * SS * DD;
    const __half* Qh = g_qh + bhoff + (long)qt * 128 * DD;
    const __half* Ql = g_ql + bhoff + (long)qt * 128 * DD;
    const __half* srcs[3] = { g_kh + bhoff, g_vh + bhoff, g_vl + bhoff };

    // Q tiles (hi, lo)
    #pragma unroll
    for (int v = 0; v < 4; v++) {
        int f = tid + 256 * v;
        int row = f >> 3, seg = f & 7;
        uint32_t boff = (uint32_t)(row * 128 + seg * 16);
        uint32_t sw = boff ^ ((boff >> 3) & 0x70);
        const __half* s0 = Qh + (long)row * DD + seg * 8;
        const __half* s1 = Ql + (long)row * DD + seg * 8;
        asm volatile("cp.async.cg.shared.global [%0], [%1], 16;"
                     :: "r"(sbase + ATT_QH + sw), "l"(s0) : "memory");
        asm volatile("cp.async.cg.shared.global [%0], [%1], 16;"
                     :: "r"(sbase + ATT_QL + sw), "l"(s1) : "memory");
    }
    asm volatile("cp.async.commit_group;" ::: "memory");

    auto stage_kv = [&](int c, int buf) {
        const uint32_t dst = sbase + ATT_STG + buf * KV_STAGE;
        const long j0 = (long)c * 64;
        #pragma unroll
        for (int t = 0; t < 3; t++) {
            const __half* src = srcs[t] + j0 * DD;
            #pragma unroll
            for (int v = 0; v < 2; v++) {
                int f = tid + 256 * v;
                int row = f >> 3, seg = f & 7;
                uint32_t boff = (uint32_t)(row * 128 + seg * 16);
                uint32_t sw = dst + t * KV_TILE + (boff ^ ((boff >> 3) & 0x70));
                const __half* s = src + (long)row * DD + seg * 8;
                asm volatile("cp.async.cg.shared.global [%0], [%1], 16;"
                             :: "r"(sw), "l"(s) : "memory");
            }
        }
        asm volatile("cp.async.commit_group;" ::: "memory");
    };

    stage_kv(0, 0);

    float m0r = -1e30f, m1r = -1e30f, l0s = 0.f, l1s = 0.f;
    float oacc[8][4];
    #pragma unroll
    for (int nf = 0; nf < 8; nf++)
        #pragma unroll
        for (int c = 0; c < 4; c++) oacc[nf][c] = 0.f;

    for (int c = 0; c < 16; c++) {
        const int buf = c & 1;
        if (c + 1 < 16) {
            stage_kv(c + 1, buf ^ 1);
            asm volatile("cp.async.wait_group 1;" ::: "memory");
        } else {
            asm volatile("cp.async.wait_group 0;" ::: "memory");
        }
        __syncthreads();

        const uint32_t stg = sbase + ATT_STG + buf * KV_STAGE;
        const uint32_t sKh = stg;
        const uint32_t sVh = stg + KV_TILE;
        const uint32_t sVl = stg + 2 * KV_TILE;

        // ---- S = (Qh+Ql) Kh^T  (log2-domain scores) ----
        float sacc[8][4];
        #pragma unroll
        for (int nf = 0; nf < 8; nf++)
            #pragma unroll
            for (int cc = 0; cc < 4; cc++) sacc[nf][cc] = 0.f;

        #pragma unroll
        for (int ks = 0; ks < 4; ks++) {
            const int k0 = ks * 16;
            uint32_t ah[4], al[4];
            ldsm_a(ah, sbase + ATT_QH, wm, k0, lid);
            ldsm_a(al, sbase + ATT_QL, wm, k0, lid);
            #pragma unroll
            for (int q = 0; q < 4; q++) {
                uint32_t bh[4];
                ldsm_b(bh, sKh, q * 16, k0, lid);
                mma_f16(sacc[2 * q],     ah, &bh[0]);
                mma_f16(sacc[2 * q],     al, &bh[0]);
                mma_f16(sacc[2 * q + 1], ah, &bh[2]);
                mma_f16(sacc[2 * q + 1], al, &bh[2]);
            }
        }

        // ---- online softmax in log2 domain (rows gID, gID+8) ----
        float mx0 = -1e30f, mx1 = -1e30f;
        #pragma unroll
        for (int nf = 0; nf < 8; nf++) {
            mx0 = fmaxf(mx0, fmaxf(sacc[nf][0], sacc[nf][1]));
            mx1 = fmaxf(mx1, fmaxf(sacc[nf][2], sacc[nf][3]));
        }
        #pragma unroll
        for (int off = 1; off <= 2; off <<= 1) {
            mx0 = fmaxf(mx0, __shfl_xor_sync(0xffffffffu, mx0, off));
            mx1 = fmaxf(mx1, __shfl_xor_sync(0xffffffffu, mx1, off));
        }
        float mn0 = fmaxf(m0r, mx0);
        float mn1 = fmaxf(m1r, mx1);
        float corr0 = ex2f(m0r - mn0);
        float corr1 = ex2f(m1r - mn1);
        float s0 = 0.f, s1 = 0.f;
        #pragma unroll
        for (int nf = 0; nf < 8; nf++) {
            float p0 = ex2f(sacc[nf][0] - mn0);
            float p1 = ex2f(sacc[nf][1] - mn0);
            float p2 = ex2f(sacc[nf][2] - mn1);
            float p3 = ex2f(sacc[nf][3] - mn1);
            sacc[nf][0] = p0; sacc[nf][1] = p1;
            sacc[nf][2] = p2; sacc[nf][3] = p3;
            s0 += p0 + p1; s1 += p2 + p3;
        }
        #pragma unroll
        for (int off = 1; off <= 2; off <<= 1) {
            s0 += __shfl_xor_sync(0xffffffffu, s0, off);
            s1 += __shfl_xor_sync(0xffffffffu, s1, off);
        }
        l0s = l0s * corr0 + s0;  m0r = mn0;
        l1s = l1s * corr1 + s1;  m1r = mn1;
        #pragma unroll
        for (int nf = 0; nf < 8; nf++) {
            oacc[nf][0] *= corr0; oacc[nf][1] *= corr0;
            oacc[nf][2] *= corr1; oacc[nf][3] *= corr1;
        }

        // ---- O += Ph (Vh + Vl), P packed hi-only ----
        #pragma unroll
        for (int kf = 0; kf < 4; kf++) {
            uint32_t pah[4];
            {
                const float* f0 = sacc[2 * kf];
                const float* f1 = sacc[2 * kf + 1];
                pah[0] = pack_f16(f0[0], f0[1]);
                pah[1] = pack_f16(f0[2], f0[3]);
                pah[2] = pack_f16(f1[0], f1[1]);
                pah[3] = pack_f16(f1[2], f1[3]);
            }
            #pragma unroll
            for (int q = 0; q < 4; q++) {
                uint32_t vh[4], vl[4];
                ldsm_v(vh, sVh, kf * 16, q * 16, lid);
                ldsm_v(vl, sVl, kf * 16, q * 16, lid);
                mma_f16(oacc[2 * q],     pah, &vh[0]);
                mma_f16(oacc[2 * q],     pah, &vl[0]);
                mma_f16(oacc[2 * q + 1], pah, &vh[2]);
                mma_f16(oacc[2 * q + 1], pah, &vl[2]);
            }
        }
        __syncthreads();
    }

    // ---- normalize + write O fp32 [B,S,E] ----
    const float inv0 = 1.f / l0s, inv1 = 1.f / l1s;
    const int i0g = qt * 128 + wm + gID;
    const int i1g = i0g + 8;
    #pragma unroll
    for (int nf = 0; nf < 8; nf++) {
        const int d = h * 64 + nf * 8 + tig * 2;
        float* p0 = g_o + (long)(b * SS + i0g) * EE + d;
        float* p1 = g_o + (long)(b * SS + i1g) * EE + d;
        *(float2*)p0 = make_float2(oacc[nf][0] * inv0, oacc[nf][1] * inv0);
        *(float2*)p1 = make_float2(oacc[nf][2] * inv1, oacc[nf][3] * inv1);
    }
}

// ---------------------------------------------------------------------------
// Kernel 3: y = LN(x + attn_out) * gamma + beta — unchanged
// ---------------------------------------------------------------------------
__global__ __launch_bounds__(256) void ln_kernel(
    const float* __restrict__ X,
    const float* __restrict__ gamma,
    const float* __restrict__ beta,
    float* __restrict__ out)
{
    __shared__ float ssum[8], ssq[8];
    const int row = blockIdx.x;
    const int tid = (int)threadIdx.x;
    const float* xr = X + (long)row * EE;
    const float* orow = g_o + (long)row * EE;

    float y[3];
    float sum = 0.f, sq = 0.f;
    #pragma unroll
    for (int r = 0; r < 3; r++) {
        int e = tid + 256 * r;
        float v = xr[e] + orow[e];
        y[r] = v;
        sum += v;
        sq += v * v;
    }
    #pragma unroll
    for (int off = 16; off >= 1; off >>= 1) {
        sum += __shfl_xor_sync(0xffffffffu, sum, off);
        sq  += __shfl_xor_sync(0xffffffffu, sq, off);
    }
    int warp = tid >> 5, lane = tid & 31;
    if (lane == 0) { ssum[warp] = sum; ssq[warp] = sq; }
    __syncthreads();
    if (warp == 0) {
        float s = (lane < 8) ? ssum[lane] : 0.f;
        float q = (lane < 8) ? ssq[lane] : 0.f;
        #pragma unroll
        for (int off = 4; off >= 1; off >>= 1) {
            s += __shfl_xor_sync(0xffffffffu, s, off);
            q += __shfl_xor_sync(0xffffffffu, q, off);
        }
        if (lane == 0) { ssum[0] = s; ssq[0] = q; }
    }
    __syncthreads();
    const float inv_e = 1.f / (float)EE;
    float mean = ssum[0] * inv_e;
    float var  = ssq[0] * inv_e - mean * mean;
    float rstd = rsqrtf(var + 1e-5f);
    #pragma unroll
    for (int r = 0; r < 3; r++) {
        int e = tid + 256 * r;
        out[(long)row * EE + e] = (y[r] - mean) * rstd * gamma[e] + beta[e];
    }
}

// ---------------------------------------------------------------------------
extern "C" void kernel_launch(void* const* d_in, const int* in_sizes, int n_in,
                              void* d_out, int out_size)
{
    const float* x     = (const float*)d_in[0];
    const float* w_qkv = (const float*)d_in[1];
    const float* b_qkv = (const float*)d_in[2];
    const float* gamma = (const float*)d_in[3];
    const float* beta  = (const float*)d_in[4];
    float* out = (float*)d_out;

    cudaFuncSetAttribute(qkv_gemm_tc,
                         cudaFuncAttributeMaxDynamicSharedMemorySize, GEMM_DYN_SMEM);
    cudaFuncSetAttribute(attn_tc,
                         cudaFuncAttributeMaxDynamicSharedMemorySize, ATT_DYN);

    cvt_x_kernel<<<(MTOT * EE) / 1024, 256>>>(x);
    cvt_w_kernel<<<dim3(N3 / 32, EE / 32), 256>>>(w_qkv);

    dim3 g1(N3 / 128, MTOT / 128);          // 18 x 64
    qkv_gemm_tc<<<g1, 256, GEMM_DYN_SMEM>>>(b_qkv);

    dim3 g2(SS / 128, HH, BB);              // 8 x 12 x 8
    attn_tc<<<g2, 256, ATT_DYN>>>();

    ln_kernel<<<MTOT, 256>>>(x, gamma, beta, out);
}

// round 15
// speedup vs baseline: 7.5713x; 1.5964x over previous
#include <cuda_runtime.h>
#include <cuda_fp16.h>
#include <cstdint>

#define BB 8
#define SS 1024
#define EE 768
#define HH 12
#define DD 64
#define MTOT (BB*SS)      // 8192
#define N3 (3*EE)         // 2304

// 0.125 * log2(e): folded into Q so softmax runs in log2 domain
#define QSCALE 0.18033688011112042f

// ------------------------- scratch (__device__ globals) ---------------------
__device__ float g_o[BB*SS*EE];      // attention output [B,S,E] fp32

__device__ __half g_xh[(long)MTOT*EE];  // X fp16
__device__ __half g_wh[(long)N3*EE];    // W^T fp16 [N3][EE] (K-major)

// Q/K/V fp16, [B,H,S,D]. Q pre-scaled by QSCALE.
__device__ __half g_qh[(long)BB*HH*SS*DD];
__device__ __half g_kh[(long)BB*HH*SS*DD];
__device__ __half g_vh[(long)BB*HH*SS*DD];

// ---------------------------------------------------------------------------
// Conversion kernels
// ---------------------------------------------------------------------------
__global__ __launch_bounds__(256) void cvt_x_kernel(const float* __restrict__ X)
{
    long i = ((long)blockIdx.x * 256 + threadIdx.x) * 4;
    float4 v = *(const float4*)(X + i);
    *(__half2*)(g_xh + i)     = __floats2half2_rn(v.x, v.y);
    *(__half2*)(g_xh + i + 2) = __floats2half2_rn(v.z, v.w);
}

__global__ __launch_bounds__(256) void cvt_w_kernel(const float* __restrict__ W)
{
    __shared__ float t[32][33];
    const int n0 = blockIdx.x * 32;
    const int k0 = blockIdx.y * 32;
    const int tx = threadIdx.x & 31;
    const int ty = threadIdx.x >> 5;   // 0..7
    #pragma unroll
    for (int r = 0; r < 4; r++) {
        int k = k0 + ty + 8 * r;
        t[ty + 8 * r][tx] = W[(long)k * N3 + n0 + tx];
    }
    __syncthreads();
    #pragma unroll
    for (int r = 0; r < 4; r++) {
        int n = n0 + ty + 8 * r;
        g_wh[(long)n * EE + k0 + tx] = __float2half_rn(t[tx][ty + 8 * r]);
    }
}

// ------------------------- mma.sync helpers ---------------------------------
__device__ __forceinline__ void mma_f16(float* c, const uint32_t* a, const uint32_t* b)
{
    asm volatile(
        "mma.sync.aligned.m16n8k16.row.col.f32.f16.f16.f32 "
        "{%0,%1,%2,%3}, {%4,%5,%6,%7}, {%8,%9}, {%0,%1,%2,%3};"
        : "+f"(c[0]), "+f"(c[1]), "+f"(c[2]), "+f"(c[3])
        : "r"(a[0]), "r"(a[1]), "r"(a[2]), "r"(a[3]), "r"(b[0]), "r"(b[1]));
}

// A fragment (m16k16) from SW128-swizzled [rows][64 f16] tile.
__device__ __forceinline__ void ldsm_a(uint32_t* r, uint32_t tb, int rm, int k0, int lane)
{
    int mat = lane >> 3, rr = lane & 7;
    int row = rm + rr + (mat & 1) * 8;
    int kb  = (k0 + (mat >> 1) * 8) * 2;
    uint32_t boff = (uint32_t)(row * 128 + kb);
    uint32_t addr = tb + (boff ^ ((boff >> 3) & 0x70));
    asm volatile("ldmatrix.sync.aligned.m8n8.x4.shared.b16 {%0,%1,%2,%3}, [%4];"
                 : "=r"(r[0]), "=r"(r[1]), "=r"(r[2]), "=r"(r[3]) : "r"(addr));
}

// Two B fragments (k16n8) for n rows nb..nb+15 from [n][64 f16] K-major tile.
__device__ __forceinline__ void ldsm_b(uint32_t* r, uint32_t tb, int nb, int k0, int lane)
{
    int mat = lane >> 3, rr = lane & 7;
    int row = nb + rr + (mat >> 1) * 8;
    int kb  = (k0 + (mat & 1) * 8) * 2;
    uint32_t boff = (uint32_t)(row * 128 + kb);
    uint32_t addr = tb + (boff ^ ((boff >> 3) & 0x70));
    asm volatile("ldmatrix.sync.aligned.m8n8.x4.shared.b16 {%0,%1,%2,%3}, [%4];"
                 : "=r"(r[0]), "=r"(r[1]), "=r"(r[2]), "=r"(r[3]) : "r"(addr));
}

// V fragments via ldmatrix.trans on row-major [j][64 d] tile (128B rows, SW128).
__device__ __forceinline__ void ldsm_v(uint32_t* r, uint32_t tb, int j0, int d0, int lane)
{
    int mat = lane >> 3, rr = lane & 7;
    int row = j0 + rr + (mat & 1) * 8;
    int db  = (d0 + (mat >> 1) * 8) * 2;
    uint32_t boff = (uint32_t)(row * 128 + db);
    uint32_t addr = tb + (boff ^ ((boff >> 3) & 0x70));
    asm volatile("ldmatrix.sync.aligned.m8n8.x4.trans.shared.b16 {%0,%1,%2,%3}, [%4];"
                 : "=r"(r[0]), "=r"(r[1]), "=r"(r[2]), "=r"(r[3]) : "r"(addr));
}

__device__ __forceinline__ uint32_t pack_f16(float lo, float hi)
{
    uint32_t u;
    asm("cvt.rn.f16x2.f32 %0, %1, %2;" : "=r"(u) : "f"(hi), "f"(lo));
    return u;
}

__device__ __forceinline__ float ex2f(float x)
{
    float y;
    asm("ex2.approx.f32 %0, %1;" : "=f"(y) : "f"(x));
    return y;
}

// ---------------------------------------------------------------------------
// Kernel 1: QKV GEMM, fp16 mma.sync: C = Xh*Wh + bias.
// Epilogue: Q -> *QSCALE; scatter fp16 [B,H,S,D].
// ---------------------------------------------------------------------------
#define QTILE_BYTES 16384            // 128 rows * 128B (64 f16 swizzled)
#define QSTAGE (2*QTILE_BYTES)       // Ah, Bh
#define GEMM_DYN_SMEM (2*QSTAGE)     // 65536

__global__ __launch_bounds__(256, 2) void qkv_gemm_tc(const float* __restrict__ bias)
{
    extern __shared__ __align__(128) char smem[];
    const uint32_t sbase = (uint32_t)__cvta_generic_to_shared(smem);
    const int tid = (int)threadIdx.x;
    const int wid = tid >> 5, lid = tid & 31;
    const int n0 = blockIdx.x * 128;
    const int m0 = blockIdx.y * 128;

    const int wm = (wid & 3) * 32;
    const int wn = (wid >> 2) * 64;

    const __half* __restrict__ srcA = g_xh + (long)m0 * EE;
    const __half* __restrict__ srcB = g_wh + (long)n0 * EE;

    auto stage_load = [&](int chunk, int buf) {
        const int k0 = chunk * 64;
        const uint32_t dstbase = sbase + buf * QSTAGE;
        #pragma unroll
        for (int t = 0; t < 2; t++) {
            const __half* src = (t == 0 ? srcA : srcB) + k0;
            const uint32_t dtile = dstbase + t * QTILE_BYTES;
            #pragma unroll
            for (int v = 0; v < 4; v++) {
                int f = tid + 256 * v;
                int row = f >> 3;
                int seg = f & 7;
                uint32_t boff = (uint32_t)(row * 128 + seg * 16);
                uint32_t sw = dtile + (boff ^ ((boff >> 3) & 0x70));
                const __half* s = src + (long)row * EE + seg * 8;
                asm volatile("cp.async.cg.shared.global [%0], [%1], 16;"
                             :: "r"(sw), "l"(s) : "memory");
            }
        }
        asm volatile("cp.async.commit_group;" ::: "memory");
    };

    float acc[2][8][4];
    #pragma unroll
    for (int mf = 0; mf < 2; mf++)
        #pragma unroll
        for (int nf = 0; nf < 8; nf++)
            #pragma unroll
            for (int c = 0; c < 4; c++) acc[mf][nf][c] = 0.f;

    stage_load(0, 0);

    for (int chunk = 0; chunk < 12; chunk++) {
        const int buf = chunk & 1;
        if (chunk + 1 < 12) {
            stage_load(chunk + 1, buf ^ 1);
            asm volatile("cp.async.wait_group 1;" ::: "memory");
        } else {
            asm volatile("cp.async.wait_group 0;" ::: "memory");
        }
        __syncthreads();

        const uint32_t stg = sbase + buf * QSTAGE;
        const uint32_t sAh = stg;
        const uint32_t sBh = stg + QTILE_BYTES;

        #pragma unroll
        for (int ks = 0; ks < 4; ks++) {
            const int k0 = ks * 16;
            uint32_t ah[2][4], bh[4][4];
            ldsm_a(ah[0], sAh, wm, k0, lid);
            ldsm_a(ah[1], sAh, wm + 16, k0, lid);
            #pragma unroll
            for (int q = 0; q < 4; q++)
                ldsm_b(bh[q], sBh, wn + q * 16, k0, lid);
            #pragma unroll
            for (int mf = 0; mf < 2; mf++)
                #pragma unroll
                for (int nf = 0; nf < 8; nf++)
                    mma_f16(acc[mf][nf], ah[mf], &bh[nf >> 1][(nf & 1) * 2]);
        }
        __syncthreads();
    }

    // ---- Epilogue: +bias, Q scale, scatter fp16 [B,H,S,D] ----
    const int gID = lid >> 2, tig = lid & 3;
    const int nbase = n0 + wn;                 // multiple of 64 -> one head
    const int which = nbase / EE;              // 0=q 1=k 2=v
    const int h = (nbase - which * EE) >> 6;

    __half* dh = (which == 0) ? g_qh : ((which == 1) ? g_kh : g_vh);
    const float sc = (which == 0) ? QSCALE : 1.f;

    #pragma unroll
    for (int mf = 0; mf < 2; mf++) {
        const int m = m0 + wm + mf * 16 + gID;
        const int b0_ = m >> 10,       s0_ = m & 1023;
        const int b1_ = (m + 8) >> 10, s1_ = (m + 8) & 1023;
        const long i0 = ((long)(b0_ * HH + h) * SS + s0_) * DD;
        const long i1 = ((long)(b1_ * HH + h) * SS + s1_) * DD;
        #pragma unroll
        for (int nf = 0; nf < 8; nf++) {
            const int d = nf * 8 + tig * 2;
            float2 bv = *(const float2*)&bias[nbase + d];
            float a0 = (acc[mf][nf][0] + bv.x) * sc;
            float a1 = (acc[mf][nf][1] + bv.y) * sc;
            float a2 = (acc[mf][nf][2] + bv.x) * sc;
            float a3 = (acc[mf][nf][3] + bv.y) * sc;
            *(uint32_t*)(dh + i0 + d) = pack_f16(a0, a1);
            *(uint32_t*)(dh + i1 + d) = pack_f16(a2, a3);
        }
    }
}

// ---------------------------------------------------------------------------
// Kernel 2: flash attention, fp16 mma.sync (single-term).
// S = Qh*Kh (log2 domain, Q pre-scaled); O += Ph*Vh.
// CTA = 128 queries x one (b,h); 16 KV chunks of 64, double-buffered cp.async.
// ---------------------------------------------------------------------------
#define KV_TILE   8192                 // 64 rows * 128B
#define KV_STAGE  (2*KV_TILE)          // Kh, Vh
#define ATT_QH    0
#define ATT_STG   16384
#define ATT_DYN   (16384 + 2*KV_STAGE) // 49152

__global__ __launch_bounds__(256, 2) void attn_tc()
{
    extern __shared__ __align__(128) char smem[];
    const uint32_t sbase = (uint32_t)__cvta_generic_to_shared(smem);
    const int tid = (int)threadIdx.x;
    const int wid = tid >> 5, lid = tid & 31;
    const int gID = lid >> 2, tig = lid & 3;
    const int qt = blockIdx.x;       // 0..7
    const int h  = blockIdx.y;
    const int b  = blockIdx.z;
    const int wm = wid * 16;

    const long bhoff = (long)(b * HH + h) * SS * DD;
    const __half* Qh = g_qh + bhoff + (long)qt * 128 * DD;
    const __half* Kh = g_kh + bhoff;
    const __half* Vh = g_vh + bhoff;

    // Q tile
    #pragma unroll
    for (int v = 0; v < 4; v++) {
        int f = tid + 256 * v;
        int row = f >> 3, seg = f & 7;
        uint32_t boff = (uint32_t)(row * 128 + seg * 16);
        uint32_t sw = boff ^ ((boff >> 3) & 0x70);
        const __half* s0 = Qh + (long)row * DD + seg * 8;
        asm volatile("cp.async.cg.shared.global [%0], [%1], 16;"
                     :: "r"(sbase + ATT_QH + sw), "l"(s0) : "memory");
    }
    asm volatile("cp.async.commit_group;" ::: "memory");

    auto stage_kv = [&](int c, int buf) {
        const uint32_t dst = sbase + ATT_STG + buf * KV_STAGE;
        const long j0 = (long)c * 64;
        #pragma unroll
        for (int t = 0; t < 2; t++) {
            const __half* src = (t == 0 ? Kh : Vh) + j0 * DD;
            #pragma unroll
            for (int v = 0; v < 2; v++) {
                int f = tid + 256 * v;
                int row = f >> 3, seg = f & 7;
                uint32_t boff = (uint32_t)(row * 128 + seg * 16);
                uint32_t sw = dst + t * KV_TILE + (boff ^ ((boff >> 3) & 0x70));
                const __half* s = src + (long)row * DD + seg * 8;
                asm volatile("cp.async.cg.shared.global [%0], [%1], 16;"
                             :: "r"(sw), "l"(s) : "memory");
            }
        }
        asm volatile("cp.async.commit_group;" ::: "memory");
    };

    stage_kv(0, 0);

    float m0r = -1e30f, m1r = -1e30f, l0s = 0.f, l1s = 0.f;
    float oacc[8][4];
    #pragma unroll
    for (int nf = 0; nf < 8; nf++)
        #pragma unroll
        for (int c = 0; c < 4; c++) oacc[nf][c] = 0.f;

    for (int c = 0; c < 16; c++) {
        const int buf = c & 1;
        if (c + 1 < 16) {
            stage_kv(c + 1, buf ^ 1);
            asm volatile("cp.async.wait_group 1;" ::: "memory");
        } else {
            asm volatile("cp.async.wait_group 0;" ::: "memory");
        }
        __syncthreads();

        const uint32_t stg = sbase + ATT_STG + buf * KV_STAGE;
        const uint32_t sKh = stg;
        const uint32_t sVh = stg + KV_TILE;

        // ---- S = Qh Kh^T  (log2-domain scores) ----
        float sacc[8][4];
        #pragma unroll
        for (int nf = 0; nf < 8; nf++)
            #pragma unroll
            for (int cc = 0; cc < 4; cc++) sacc[nf][cc] = 0.f;

        #pragma unroll
        for (int ks = 0; ks < 4; ks++) {
            const int k0 = ks * 16;
            uint32_t ah[4];
            ldsm_a(ah, sbase + ATT_QH, wm, k0, lid);
            #pragma unroll
            for (int q = 0; q < 4; q++) {
                uint32_t bh[4];
                ldsm_b(bh, sKh, q * 16, k0, lid);
                mma_f16(sacc[2 * q],     ah, &bh[0]);
                mma_f16(sacc[2 * q + 1], ah, &bh[2]);
            }
        }

        // ---- online softmax in log2 domain (rows gID, gID+8) ----
        float mx0 = -1e30f, mx1 = -1e30f;
        #pragma unroll
        for (int nf = 0; nf < 8; nf++) {
            mx0 = fmaxf(mx0, fmaxf(sacc[nf][0], sacc[nf][1]));
            mx1 = fmaxf(mx1, fmaxf(sacc[nf][2], sacc[nf][3]));
        }
        #pragma unroll
        for (int off = 1; off <= 2; off <<= 1) {
            mx0 = fmaxf(mx0, __shfl_xor_sync(0xffffffffu, mx0, off));
            mx1 = fmaxf(mx1, __shfl_xor_sync(0xffffffffu, mx1, off));
        }
        float mn0 = fmaxf(m0r, mx0);
        float mn1 = fmaxf(m1r, mx1);
        float corr0 = ex2f(m0r - mn0);
        float corr1 = ex2f(m1r - mn1);
        float s0 = 0.f, s1 = 0.f;
        #pragma unroll
        for (int nf = 0; nf < 8; nf++) {
            float p0 = ex2f(sacc[nf][0] - mn0);
            float p1 = ex2f(sacc[nf][1] - mn0);
            float p2 = ex2f(sacc[nf][2] - mn1);
            float p3 = ex2f(sacc[nf][3] - mn1);
            sacc[nf][0] = p0; sacc[nf][1] = p1;
            sacc[nf][2] = p2; sacc[nf][3] = p3;
            s0 += p0 + p1; s1 += p2 + p3;
        }
        #pragma unroll
        for (int off = 1; off <= 2; off <<= 1) {
            s0 += __shfl_xor_sync(0xffffffffu, s0, off);
            s1 += __shfl_xor_sync(0xffffffffu, s1, off);
        }
        l0s = l0s * corr0 + s0;  m0r = mn0;
        l1s = l1s * corr1 + s1;  m1r = mn1;
        #pragma unroll
        for (int nf = 0; nf < 8; nf++) {
            oacc[nf][0] *= corr0; oacc[nf][1] *= corr0;
            oacc[nf][2] *= corr1; oacc[nf][3] *= corr1;
        }

        // ---- O += Ph Vh ----
        #pragma unroll
        for (int kf = 0; kf < 4; kf++) {
            uint32_t pah[4];
            {
                const float* f0 = sacc[2 * kf];
                const float* f1 = sacc[2 * kf + 1];
                pah[0] = pack_f16(f0[0], f0[1]);
                pah[1] = pack_f16(f0[2], f0[3]);
                pah[2] = pack_f16(f1[0], f1[1]);
                pah[3] = pack_f16(f1[2], f1[3]);
            }
            #pragma unroll
            for (int q = 0; q < 4; q++) {
                uint32_t vh[4];
                ldsm_v(vh, sVh, kf * 16, q * 16, lid);
                mma_f16(oacc[2 * q],     pah, &vh[0]);
                mma_f16(oacc[2 * q + 1], pah, &vh[2]);
            }
        }
        __syncthreads();
    }

    // ---- normalize + write O fp32 [B,S,E] ----
    const float inv0 = 1.f / l0s, inv1 = 1.f / l1s;
    const int i0g = qt * 128 + wm + gID;
    const int i1g = i0g + 8;
    #pragma unroll
    for (int nf = 0; nf < 8; nf++) {
        const int d = h * 64 + nf * 8 + tig * 2;
        float* p0 = g_o + (long)(b * SS + i0g) * EE + d;
        float* p1 = g_o + (long)(b * SS + i1g) * EE + d;
        *(float2*)p0 = make_float2(oacc[nf][0] * inv0, oacc[nf][1] * inv0);
        *(float2*)p1 = make_float2(oacc[nf][2] * inv1, oacc[nf][3] * inv1);
    }
}

// ---------------------------------------------------------------------------
// Kernel 3: y = LN(x + attn_out) * gamma + beta — unchanged
// ---------------------------------------------------------------------------
__global__ __launch_bounds__(256) void ln_kernel(
    const float* __restrict__ X,
    const float* __restrict__ gamma,
    const float* __restrict__ beta,
    float* __restrict__ out)
{
    __shared__ float ssum[8], ssq[8];
    const int row = blockIdx.x;
    const int tid = (int)threadIdx.x;
    const float* xr = X + (long)row * EE;
    const float* orow = g_o + (long)row * EE;

    float y[3];
    float sum = 0.f, sq = 0.f;
    #pragma unroll
    for (int r = 0; r < 3; r++) {
        int e = tid + 256 * r;
        float v = xr[e] + orow[e];
        y[r] = v;
        sum += v;
        sq += v * v;
    }
    #pragma unroll
    for (int off = 16; off >= 1; off >>= 1) {
        sum += __shfl_xor_sync(0xffffffffu, sum, off);
        sq  += __shfl_xor_sync(0xffffffffu, sq, off);
    }
    int warp = tid >> 5, lane = tid & 31;
    if (lane == 0) { ssum[warp] = sum; ssq[warp] = sq; }
    __syncthreads();
    if (warp == 0) {
        float s = (lane < 8) ? ssum[lane] : 0.f;
        float q = (lane < 8) ? ssq[lane] : 0.f;
        #pragma unroll
        for (int off = 4; off >= 1; off >>= 1) {
            s += __shfl_xor_sync(0xffffffffu, s, off);
            q += __shfl_xor_sync(0xffffffffu, q, off);
        }
        if (lane == 0) { ssum[0] = s; ssq[0] = q; }
    }
    __syncthreads();
    const float inv_e = 1.f / (float)EE;
    float mean = ssum[0] * inv_e;
    float var  = ssq[0] * inv_e - mean * mean;
    float rstd = rsqrtf(var + 1e-5f);
    #pragma unroll
    for (int r = 0; r < 3; r++) {
        int e = tid + 256 * r;
        out[(long)row * EE + e] = (y[r] - mean) * rstd * gamma[e] + beta[e];
    }
}

// ---------------------------------------------------------------------------
extern "C" void kernel_launch(void* const* d_in, const int* in_sizes, int n_in,
                              void* d_out, int out_size)
{
    const float* x     = (const float*)d_in[0];
    const float* w_qkv = (const float*)d_in[1];
    const float* b_qkv = (const float*)d_in[2];
    const float* gamma = (const float*)d_in[3];
    const float* beta  = (const float*)d_in[4];
    float* out = (float*)d_out;

    cudaFuncSetAttribute(qkv_gemm_tc,
                         cudaFuncAttributeMaxDynamicSharedMemorySize, GEMM_DYN_SMEM);
    cudaFuncSetAttribute(attn_tc,
                         cudaFuncAttributeMaxDynamicSharedMemorySize, ATT_DYN);

    cvt_x_kernel<<<(MTOT * EE) / 1024, 256>>>(x);
    cvt_w_kernel<<<dim3(N3 / 32, EE / 32), 256>>>(w_qkv);

    dim3 g1(N3 / 128, MTOT / 128);          // 18 x 64
    qkv_gemm_tc<<<g1, 256, GEMM_DYN_SMEM>>>(b_qkv);

    dim3 g2(SS / 128, HH, BB);              // 8 x 12 x 8
    attn_tc<<<g2, 256, ATT_DYN>>>();

    ln_kernel<<<MTOT, 256>>>(x, gamma, beta, out);
}